// round 11
// baseline (speedup 1.0000x reference)
#include <cuda_runtime.h>
#include <cuda_bf16.h>
#include <math.h>
#include <stdint.h>

#define NN 50000
#define CC 256
#define HH 4
#define DD 64
#define EE 800000
#define OC 256   // H*D
#define FNN 50000.0f

// ---------------- device scratch ----------------
__device__ float g_q[NN * OC];
__device__ float g_vbar[NN * DD];
__device__ float g_S[OC * OC];       // Xs^T Xs
__device__ float g_T[OC * OC];       // Wk @ S
__device__ float g_xsum[OC];
__device__ float g_wvbar[DD * CC];
__device__ float g_bvbar[DD];
__device__ float g_ksum[OC];
__device__ float g_vsum[OC];
__device__ float g_kv[HH * DD * DD]; // [h][d][m]
__device__ float g_scal[2];
__device__ float g_deg[NN];
__device__ int   g_offs[NN + 1];
__device__ int   g_cursor[NN];
__device__ int   g_src[EE];
__device__ float g_val[EE];
__device__ int   g_part[256];
__device__ int   g_cnt[16];
__device__ int   g_ticket;

// dependency counters
#define C_SYRK 0
#define C_GEMQ 1
#define C_VBAR 2
#define C_DEG  3
#define C_FIXT 4
#define C_SUMV 5
#define C_SC1  6
#define C_SC2  7
#define C_SC3  8
#define C_KV   9
#define C_KSQ  10

__device__ __forceinline__ void done_inc(int idx) {
    __threadfence();
    __syncthreads();
    if (threadIdx.x == 0) atomicAdd(&g_cnt[idx], 1);
}
__device__ __forceinline__ void spin_on(int idx, int target) {
    if (threadIdx.x == 0) {
        while (atomicAdd(&g_cnt[idx], 0) < target) { __nanosleep(128); }
    }
    __syncthreads();
}

// ---------------- helpers ----------------
__device__ __forceinline__ uint32_t f2tf32(float x) {
    uint32_t r;
    asm("cvt.rna.tf32.f32 %0, %1;" : "=r"(r) : "f"(x));
    return r;
}
__device__ __forceinline__ uint32_t pk(float lo, float hi) {
    uint32_t r;
    asm("cvt.rn.bf16x2.f32 %0, %1, %2;" : "=r"(r) : "f"(hi), "f"(lo));
    return r;
}
__device__ __forceinline__ void mma_tf32(float& d0, float& d1, float& d2, float& d3,
                                         const uint32_t* a, const uint32_t* b) {
    asm volatile(
        "mma.sync.aligned.m16n8k8.row.col.f32.tf32.tf32.f32 "
        "{%0,%1,%2,%3}, {%4,%5,%6,%7}, {%8,%9}, {%0,%1,%2,%3};\n"
        : "+f"(d0), "+f"(d1), "+f"(d2), "+f"(d3)
        : "r"(a[0]), "r"(a[1]), "r"(a[2]), "r"(a[3]), "r"(b[0]), "r"(b[1]));
}
__device__ __forceinline__ void mma_bf16(float& d0, float& d1, float& d2, float& d3,
                                         const uint32_t* a, const uint32_t* b) {
    asm volatile(
        "mma.sync.aligned.m16n8k16.row.col.f32.bf16.bf16.f32 "
        "{%0,%1,%2,%3}, {%4,%5,%6,%7}, {%8,%9}, {%0,%1,%2,%3};\n"
        : "+f"(d0), "+f"(d1), "+f"(d2), "+f"(d3)
        : "r"(a[0]), "r"(a[1]), "r"(a[2]), "r"(a[3]), "r"(b[0]), "r"(b[1]));
}

// ---------------- L1: zero scratch + counters + Wvbar prep ----------------
__global__ void zero_kernel(const float* __restrict__ Wv, const float* __restrict__ bv) {
    int i = blockIdx.x * 256 + threadIdx.x;   // 65536
    g_S[i] = 0.f;
    if (i < NN) g_deg[i] = 0.f;
    if (i < OC) g_xsum[i] = 0.f;
    if (i < 2) g_scal[i] = 0.f;
    if (i < 16) g_cnt[i] = 0;
    if (i == 16) g_ticket = 0;
    if (i < DD * CC) {
        int d = i >> 8, c = i & 255;
        g_wvbar[i] = 0.25f * (Wv[(d) * CC + c] + Wv[(d + 64) * CC + c] +
                              Wv[(d + 128) * CC + c] + Wv[(d + 192) * CC + c]);
    }
    if (i < DD)
        g_bvbar[i] = 0.25f * (bv[i] + bv[i + 64] + bv[i + 128] + bv[i + 192]);
}

// ======================== mega-kernel bodies ========================
#define BK 32
#define AST 36
#define TSZ (128 * AST)
#define SST 132
#define CHK 1024
#define NCH 49
#define QST 68

// ---- SYRK tile body ----
__device__ void syrk_body(float* smf, int bidx, const float* __restrict__ Xs) {
    float* Ai = smf;
    float* Bj = smf + 2 * 32 * SST;
    int t = threadIdx.x;
    int tile = bidx / NCH;            // 0:(0,0) 1:(0,1) 2:(1,1)
    int chunk = bidx % NCH;
    int ci = (tile == 2) ? 1 : 0;
    int cj = (tile == 0) ? 0 : 1;
    int diag = (ci == cj);
    int nbase = chunk * CHK;
    int lane = t & 31, warp = t >> 5;
    int wm = warp & 1, wn = warp >> 1;

    auto load_tile = [&](int stage, int s) {
#pragma unroll
        for (int p = 0; p < 4; p++) {
            int idx = p * 256 + t;
            int r = idx >> 5;
            int c4 = (idx & 31) * 4;
            int node = nbase + s + r;
            int ok = (node < NN);
            const float* srcA = Xs + (size_t)(ok ? node : 0) * CC + ci * 128 + c4;
            uint32_t da = (uint32_t)__cvta_generic_to_shared(&Ai[stage * 32 * SST + r * SST + c4]);
            int sz = ok ? 16 : 0;
            asm volatile("cp.async.cg.shared.global [%0], [%1], 16, %2;\n"
                         :: "r"(da), "l"(srcA), "r"(sz));
            if (!diag) {
                const float* srcB = Xs + (size_t)(ok ? node : 0) * CC + cj * 128 + c4;
                uint32_t db = (uint32_t)__cvta_generic_to_shared(&Bj[stage * 32 * SST + r * SST + c4]);
                asm volatile("cp.async.cg.shared.global [%0], [%1], 16, %2;\n"
                             :: "r"(db), "l"(srcB), "r"(sz));
            }
        }
        asm volatile("cp.async.commit_group;\n");
    };

    float d[4][4][4];
#pragma unroll
    for (int i = 0; i < 4; i++)
#pragma unroll
        for (int j = 0; j < 4; j++)
#pragma unroll
            for (int c = 0; c < 4; c++) d[i][j][c] = 0.f;

    load_tile(0, 0);
    for (int si = 0; si < CHK / 32; si++) {
        if (si < CHK / 32 - 1) {
            load_tile((si + 1) & 1, (si + 1) * 32);
            asm volatile("cp.async.wait_group 1;\n");
        } else {
            asm volatile("cp.async.wait_group 0;\n");
        }
        __syncthreads();
        const float* Af = Ai + (si & 1) * 32 * SST;
        const float* Bf = diag ? Af : (Bj + (si & 1) * 32 * SST);
#pragma unroll
        for (int kf = 0; kf < 2; kf++) {
            int k = kf * 16 + (lane & 3) * 2;
            uint32_t a[4][4], b[4][2];
#pragma unroll
            for (int mf = 0; mf < 4; mf++) {
                int ra = wm * 64 + mf * 16 + (lane >> 2);
                a[mf][0] = pk(Af[k * SST + ra],       Af[(k + 1) * SST + ra]);
                a[mf][1] = pk(Af[k * SST + ra + 8],   Af[(k + 1) * SST + ra + 8]);
                a[mf][2] = pk(Af[(k + 8) * SST + ra], Af[(k + 9) * SST + ra]);
                a[mf][3] = pk(Af[(k + 8) * SST + ra + 8], Af[(k + 9) * SST + ra + 8]);
            }
#pragma unroll
            for (int nf = 0; nf < 4; nf++) {
                int rb = wn * 32 + nf * 8 + (lane >> 2);
                b[nf][0] = pk(Bf[k * SST + rb],       Bf[(k + 1) * SST + rb]);
                b[nf][1] = pk(Bf[(k + 8) * SST + rb], Bf[(k + 9) * SST + rb]);
            }
#pragma unroll
            for (int nf = 0; nf < 4; nf++)
#pragma unroll
                for (int mf = 0; mf < 4; mf++)
                    mma_bf16(d[mf][nf][0], d[mf][nf][1], d[mf][nf][2], d[mf][nf][3],
                             a[mf], b[nf]);
        }
        __syncthreads();
    }
#pragma unroll
    for (int mf = 0; mf < 4; mf++) {
#pragma unroll
        for (int nf = 0; nf < 4; nf++) {
            int row = ci * 128 + wm * 64 + mf * 16 + (lane >> 2);
            int col = cj * 128 + wn * 32 + nf * 8 + (lane & 3) * 2;
            atomicAdd(&g_S[row * 256 + col],       d[mf][nf][0]);
            atomicAdd(&g_S[row * 256 + col + 1],   d[mf][nf][1]);
            atomicAdd(&g_S[(row + 8) * 256 + col], d[mf][nf][2]);
            atomicAdd(&g_S[(row + 8) * 256 + col + 1], d[mf][nf][3]);
        }
    }
}

// ---- Q GEMM body (bf16) ----
__device__ void gemmq_body(float* smf, int bi, const float* __restrict__ X,
                           const float* __restrict__ W, const float* __restrict__ B) {
    float* As = smf;
    float* Bs = smf + 2 * TSZ;
    __shared__ float red8[8];

    int t = threadIdx.x;
    int m0 = (bi >> 1) * 128;
    int n0 = (bi & 1) * 128;
    int lane = t & 31, warp = t >> 5;
    int wm = warp & 1, wn = warp >> 1;
    int lr = t >> 3, lc = (t & 7) * 4;

    auto load_tile = [&](int stage, int k0) {
#pragma unroll
        for (int p = 0; p < 4; p++) {
            int r = p * 32 + lr;
            int gr = m0 + r;
            int ok = (gr < NN);
            const float* srcA = X + (size_t)(ok ? gr : 0) * CC + k0 + lc;
            uint32_t da = (uint32_t)__cvta_generic_to_shared(&As[stage * TSZ + r * AST + lc]);
            int szA = ok ? 16 : 0;
            asm volatile("cp.async.cg.shared.global [%0], [%1], 16, %2;\n"
                         :: "r"(da), "l"(srcA), "r"(szA));
            const float* srcB = W + (size_t)(n0 + r) * CC + k0 + lc;
            uint32_t db = (uint32_t)__cvta_generic_to_shared(&Bs[stage * TSZ + r * AST + lc]);
            asm volatile("cp.async.cg.shared.global [%0], [%1], 16;\n"
                         :: "r"(db), "l"(srcB));
        }
        asm volatile("cp.async.commit_group;\n");
    };

    float d[4][4][4];
#pragma unroll
    for (int i = 0; i < 4; i++)
#pragma unroll
        for (int j = 0; j < 4; j++)
#pragma unroll
            for (int c = 0; c < 4; c++) d[i][j][c] = 0.f;

    load_tile(0, 0);
    for (int ki = 0; ki < CC / BK; ki++) {
        if (ki < CC / BK - 1) {
            load_tile((ki + 1) & 1, (ki + 1) * BK);
            asm volatile("cp.async.wait_group 1;\n");
        } else {
            asm volatile("cp.async.wait_group 0;\n");
        }
        __syncthreads();
        const float* Af = As + (ki & 1) * TSZ;
        const float* Bf = Bs + (ki & 1) * TSZ;
#pragma unroll
        for (int kf = 0; kf < 2; kf++) {
            int ka = kf * 16 + (lane & 3) * 2;
            uint32_t a[4][4], b[4][2];
#pragma unroll
            for (int mf = 0; mf < 4; mf++) {
                int ra = wm * 64 + mf * 16 + (lane >> 2);
                float2 x0 = *(const float2*)&Af[ra * AST + ka];
                float2 x1 = *(const float2*)&Af[(ra + 8) * AST + ka];
                float2 x2 = *(const float2*)&Af[ra * AST + ka + 8];
                float2 x3 = *(const float2*)&Af[(ra + 8) * AST + ka + 8];
                a[mf][0] = pk(x0.x, x0.y); a[mf][1] = pk(x1.x, x1.y);
                a[mf][2] = pk(x2.x, x2.y); a[mf][3] = pk(x3.x, x3.y);
            }
#pragma unroll
            for (int nf = 0; nf < 4; nf++) {
                int rb = wn * 32 + nf * 8 + (lane >> 2);
                float2 y0 = *(const float2*)&Bf[rb * AST + ka];
                float2 y1 = *(const float2*)&Bf[rb * AST + ka + 8];
                b[nf][0] = pk(y0.x, y0.y); b[nf][1] = pk(y1.x, y1.y);
            }
#pragma unroll
            for (int nf = 0; nf < 4; nf++)
#pragma unroll
                for (int mf = 0; mf < 4; mf++)
                    mma_bf16(d[mf][nf][0], d[mf][nf][1], d[mf][nf][2], d[mf][nf][3],
                             a[mf], b[nf]);
        }
        __syncthreads();
    }

    float qs = 0.f;
#pragma unroll
    for (int mf = 0; mf < 4; mf++) {
#pragma unroll
        for (int nf = 0; nf < 4; nf++) {
            int row = m0 + wm * 64 + mf * 16 + (lane >> 2);
            int col = n0 + wn * 32 + nf * 8 + (lane & 3) * 2;
            float bi0 = B[col], bi1 = B[col + 1];
            if (row < NN) {
                float o0 = d[mf][nf][0] + bi0, o1 = d[mf][nf][1] + bi1;
                *(float2*)&g_q[(size_t)row * OC + col] = make_float2(o0, o1);
                qs += o0 * o0 + o1 * o1;
            }
            if (row + 8 < NN) {
                float o0 = d[mf][nf][2] + bi0, o1 = d[mf][nf][3] + bi1;
                *(float2*)&g_q[(size_t)(row + 8) * OC + col] = make_float2(o0, o1);
                qs += o0 * o0 + o1 * o1;
            }
        }
    }
#pragma unroll
    for (int off = 16; off > 0; off >>= 1) qs += __shfl_xor_sync(0xffffffffu, qs, off);
    if (lane == 0) red8[warp] = qs;
    __syncthreads();
    if (t == 0) {
        float s = 0.f;
#pragma unroll
        for (int j = 0; j < 8; j++) s += red8[j];
        atomicAdd(&g_scal[0], s);
    }
}

// ---- vbar GEMM body (tf32) + xsum fold ----
__device__ void vbar_body(float* smf, int bi, const float* __restrict__ Xs) {
    float* As = smf;
    float* Bs = smf + 2 * TSZ;

    int t = threadIdx.x;
    int m0 = bi * 128;
    int lane = t & 31, warp = t >> 5;
    int lr = t >> 3, lc = (t & 7) * 4;

    auto load_tile = [&](int stage, int k0) {
#pragma unroll
        for (int p = 0; p < 4; p++) {
            int r = p * 32 + lr;
            int gr = m0 + r;
            int ok = (gr < NN);
            const float* srcA = Xs + (size_t)(ok ? gr : 0) * CC + k0 + lc;
            uint32_t da = (uint32_t)__cvta_generic_to_shared(&As[stage * TSZ + r * AST + lc]);
            int szA = ok ? 16 : 0;
            asm volatile("cp.async.cg.shared.global [%0], [%1], 16, %2;\n"
                         :: "r"(da), "l"(srcA), "r"(szA));
        }
#pragma unroll
        for (int p = 0; p < 2; p++) {
            int r = p * 32 + lr;
            const float* srcB = g_wvbar + (size_t)r * CC + k0 + lc;
            uint32_t db = (uint32_t)__cvta_generic_to_shared(&Bs[stage * 64 * AST + r * AST + lc]);
            asm volatile("cp.async.cg.shared.global [%0], [%1], 16;\n"
                         :: "r"(db), "l"(srcB));
        }
        asm volatile("cp.async.commit_group;\n");
    };

    float acc[8][4];
#pragma unroll
    for (int i = 0; i < 8; i++)
#pragma unroll
        for (int c = 0; c < 4; c++) acc[i][c] = 0.f;

    load_tile(0, 0);
    for (int ki = 0; ki < CC / BK; ki++) {
        if (ki < CC / BK - 1) {
            load_tile((ki + 1) & 1, (ki + 1) * BK);
            asm volatile("cp.async.wait_group 1;\n");
        } else {
            asm volatile("cp.async.wait_group 0;\n");
        }
        __syncthreads();
        const float* Af = As + (ki & 1) * TSZ;
        const float* Bf = Bs + (ki & 1) * 64 * AST;
        {
            int col = t & 31, rg = t >> 5;
            float p = 0.f;
#pragma unroll
            for (int r = 0; r < 16; r++) p += Af[(rg * 16 + r) * AST + col];
            atomicAdd(&g_xsum[ki * 32 + col], p);
        }
#pragma unroll
        for (int kf = 0; kf < 4; kf++) {
            int ka = kf * 8 + (lane & 3);
            uint32_t a[4];
            int ra = warp * 16 + (lane >> 2);
            a[0] = f2tf32(Af[ra * AST + ka]);
            a[1] = f2tf32(Af[(ra + 8) * AST + ka]);
            a[2] = f2tf32(Af[ra * AST + ka + 4]);
            a[3] = f2tf32(Af[(ra + 8) * AST + ka + 4]);
#pragma unroll
            for (int nf = 0; nf < 8; nf++) {
                int rb = nf * 8 + (lane >> 2);
                uint32_t b[2];
                b[0] = f2tf32(Bf[rb * AST + ka]);
                b[1] = f2tf32(Bf[rb * AST + ka + 4]);
                mma_tf32(acc[nf][0], acc[nf][1], acc[nf][2], acc[nf][3], a, b);
            }
        }
        __syncthreads();
    }
#pragma unroll
    for (int nf = 0; nf < 8; nf++) {
        int row = m0 + warp * 16 + (lane >> 2);
        int col = nf * 8 + (lane & 3) * 2;
        float b0 = g_bvbar[col], b1 = g_bvbar[col + 1];
        if (row < NN)
            *(float2*)&g_vbar[(size_t)row * DD + col] =
                make_float2(acc[nf][0] + b0, acc[nf][1] + b1);
        if (row + 8 < NN)
            *(float2*)&g_vbar[(size_t)(row + 8) * DD + col] =
                make_float2(acc[nf][2] + b0, acc[nf][3] + b1);
    }
}

// ---- attention body (tf32 MMA) ----
__device__ void attn_body(uint32_t* sm, int bi, float* __restrict__ out) {
    uint32_t* sq  = sm;
    uint32_t* skv = sm + 128 * QST;
    float* sden = (float*)(skv + 64 * QST);
    float* sks  = sden + 128;
    float* svs  = sks + 64;

    int t = threadIdx.x;
    int lane = t & 31, warp = t >> 5;
    int wm = warp >> 1;
    int wn = warp & 1;
    int m0 = bi * 128;
    float scal = rsqrtf(g_scal[0]) * rsqrtf(g_scal[1]);

    float facc[2][4][4];
#pragma unroll
    for (int i = 0; i < 2; i++)
#pragma unroll
        for (int j = 0; j < 4; j++)
#pragma unroll
            for (int c = 0; c < 4; c++) facc[i][j][c] = 0.f;

    for (int h = 0; h < HH; h++) {
        __syncthreads();
        {
            int r = t >> 4;
            int c = (t & 15) * 4;
#pragma unroll
            for (int p = 0; p < 8; p++) {
                int row = p * 16 + r;
                int n = m0 + row;
                float4 v = make_float4(0.f, 0.f, 0.f, 0.f);
                if (n < NN) v = *(const float4*)&g_q[(size_t)n * OC + h * 64 + c];
                uint4 u = make_uint4(f2tf32(v.x), f2tf32(v.y), f2tf32(v.z), f2tf32(v.w));
                *(uint4*)&sq[row * QST + c] = u;
            }
#pragma unroll
            for (int p = 0; p < 4; p++) {
                int row = p * 16 + r;
                float4 v = *(const float4*)&g_kv[h * 4096 + row * 64 + c];
                uint4 u = make_uint4(f2tf32(v.x), f2tf32(v.y), f2tf32(v.z), f2tf32(v.w));
                *(uint4*)&skv[row * QST + c] = u;
            }
            if (t < 64) { sks[t] = g_ksum[h * 64 + t]; svs[t] = g_vsum[h * 64 + t]; }
        }
        __syncthreads();
        {
            int r = t >> 1, p = t & 1;
            float s = 0.f;
#pragma unroll
            for (int m = 0; m < 32; m++)
                s += __uint_as_float(sq[r * QST + p * 32 + m]) * sks[p * 32 + m];
            s += __shfl_xor_sync(0xffffffffu, s, 1);
            if (p == 0) sden[r] = scal * s + FNN;
        }
        __syncthreads();

        float num[2][4][4];
#pragma unroll
        for (int i = 0; i < 2; i++)
#pragma unroll
            for (int j = 0; j < 4; j++)
#pragma unroll
                for (int c = 0; c < 4; c++) num[i][j][c] = 0.f;

#pragma unroll
        for (int kf = 0; kf < 8; kf++) {
            int ka = kf * 8 + (lane & 3);
            uint32_t a[2][4];
#pragma unroll
            for (int mf = 0; mf < 2; mf++) {
                int ra = wm * 32 + mf * 16 + (lane >> 2);
                a[mf][0] = sq[ra * QST + ka];
                a[mf][1] = sq[(ra + 8) * QST + ka];
                a[mf][2] = sq[ra * QST + ka + 4];
                a[mf][3] = sq[(ra + 8) * QST + ka + 4];
            }
#pragma unroll
            for (int nf = 0; nf < 4; nf++) {
                int rb = wn * 32 + nf * 8 + (lane >> 2);
                uint32_t b[2];
                b[0] = skv[rb * QST + ka];
                b[1] = skv[rb * QST + ka + 4];
#pragma unroll
                for (int mf = 0; mf < 2; mf++)
                    mma_tf32(num[mf][nf][0], num[mf][nf][1], num[mf][nf][2], num[mf][nf][3],
                             a[mf], b);
            }
        }
#pragma unroll
        for (int mf = 0; mf < 2; mf++) {
            int rl = wm * 32 + mf * 16 + (lane >> 2);
            float i0 = 1.f / sden[rl];
            float i1 = 1.f / sden[rl + 8];
#pragma unroll
            for (int nf = 0; nf < 4; nf++) {
                int col = wn * 32 + nf * 8 + (lane & 3) * 2;
                float s0 = svs[col], s1 = svs[col + 1];
                facc[mf][nf][0] += (scal * num[mf][nf][0] + s0) * i0;
                facc[mf][nf][1] += (scal * num[mf][nf][1] + s1) * i0;
                facc[mf][nf][2] += (scal * num[mf][nf][2] + s0) * i1;
                facc[mf][nf][3] += (scal * num[mf][nf][3] + s1) * i1;
            }
        }
    }
#pragma unroll
    for (int mf = 0; mf < 2; mf++) {
#pragma unroll
        for (int nf = 0; nf < 4; nf++) {
            int row = m0 + wm * 32 + mf * 16 + (lane >> 2);
            int col = wn * 32 + nf * 8 + (lane & 3) * 2;
            if (row < NN)
                *(float2*)&out[(size_t)row * 64 + col] =
                    make_float2(0.25f * facc[mf][nf][0], 0.25f * facc[mf][nf][1]);
            if (row + 8 < NN)
                *(float2*)&out[(size_t)(row + 8) * 64 + col] =
                    make_float2(0.25f * facc[mf][nf][2], 0.25f * facc[mf][nf][3]);
        }
    }
}

// ---- mega dispatcher (ticket-ordered jobs -> deadlock-free under any HW dispatch order) ----
#define M_SYRK 147
#define M_GEMQ (M_SYRK + 782)   // 929
#define M_VBAR (M_GEMQ + 391)   // 1320
#define M_DEG  (M_VBAR + 391)   // 1711
#define M_FIXT (M_DEG + 256)    // 1967
#define M_SUMV (M_FIXT + 2)     // 1969
#define M_SC1  (M_SUMV + 196)   // 2165
#define M_SC2  (M_SC1 + 1)      // 2166
#define M_SC3  (M_SC2 + 196)    // 2362
#define M_SCAT (M_SC3 + 784)    // 3146
#define M_KV   (M_SCAT + 2048)  // 5194
#define M_KSQ  (M_KV + 64)      // 5258
#define M_ATTN (M_KSQ + 391)    // 5649

__global__ void __launch_bounds__(256, 2)
mega(const float* __restrict__ Xq, const float* __restrict__ Wq, const float* __restrict__ bq,
     const float* __restrict__ Xs,
     const float* __restrict__ Wk, const float* __restrict__ bk,
     const float* __restrict__ Wv, const float* __restrict__ bv,
     const int* __restrict__ ei, const float* __restrict__ ew,
     float* __restrict__ out)
{
    extern __shared__ float smf[];
    __shared__ int sjob;
    int t = threadIdx.x;

    // ticket: jobs are claimed in residency order, so every job's dependencies
    // (strictly lower job ids) belong to blocks that became resident earlier.
    if (t == 0) sjob = atomicAdd(&g_ticket, 1);
    __syncthreads();
    int b = sjob;

    if (b < M_SYRK) {
        syrk_body(smf, b, Xs);
        done_inc(C_SYRK);
    } else if (b < M_GEMQ) {
        gemmq_body(smf, b - M_SYRK, Xq, Wq, bq);
        done_inc(C_GEMQ);
    } else if (b < M_VBAR) {
        vbar_body(smf, b - M_GEMQ, Xs);
        done_inc(C_VBAR);
    } else if (b < M_DEG) {
        int gs = b - M_VBAR;
        for (int e = gs * 256 + t; e < EE; e += 391 * 256)
            atomicAdd(&g_deg[ei[EE + e]], 1.0f);
        done_inc(C_DEG);
    } else if (b < M_FIXT) {
        // fixT: T = Wk @ S (symmetric read)
        spin_on(C_SYRK, 147);
        int i = b - M_DEG;
        __shared__ float w[256];
        w[t] = Wk[i * CC + t];
        __syncthreads();
        float acc = 0.f;
#pragma unroll 4
        for (int c = 0; c < 256; c++) {
            float s = (c >= 128 && t < 128) ? g_S[t * 256 + c] : g_S[c * 256 + t];
            acc += w[c] * s;
        }
        g_T[i * 256 + t] = acc;
        done_inc(C_FIXT);
    } else if (b < M_SUMV) {
        // sumvec: ksum / vsum
        spin_on(C_VBAR, 391);
        int sel = b - M_FIXT;
        __shared__ float xs[256];
        xs[t] = g_xsum[t];
        __syncthreads();
        const float* W = sel ? Wv : Wk;
        const float* bb = sel ? bv : bk;
        float* dst = sel ? g_vsum : g_ksum;
        float acc = 0.f;
#pragma unroll 4
        for (int c = 0; c < 256; c++) acc += W[t * CC + c] * xs[c];
        dst[t] = acc + FNN * bb[t];
        done_inc(C_SUMV);
    } else if (b < M_SC1) {
        spin_on(C_DEG, 391);
        int blk = b - M_SUMV;
        int i = blk * 256 + t;
        int v = (i < NN) ? (int)g_deg[i] : 0;
#pragma unroll
        for (int off = 16; off > 0; off >>= 1) v += __shfl_xor_sync(0xffffffffu, v, off);
        __shared__ int ws[8];
        if ((t & 31) == 0) ws[t >> 5] = v;
        __syncthreads();
        if (t == 0) {
            int s = 0;
#pragma unroll
            for (int j = 0; j < 8; j++) s += ws[j];
            g_part[blk] = s;
        }
        done_inc(C_SC1);
    } else if (b < M_SC2) {
        spin_on(C_SC1, 196);
        int v = (t < 196) ? g_part[t] : 0;
        int lane = t & 31, w = t >> 5;
        int x = v;
#pragma unroll
        for (int off = 1; off < 32; off <<= 1) {
            int y = __shfl_up_sync(0xffffffffu, x, off);
            if (lane >= off) x += y;
        }
        __shared__ int ws[8];
        if (lane == 31) ws[w] = x;
        __syncthreads();
        if (t == 0) {
            int c = 0;
#pragma unroll
            for (int j = 0; j < 8; j++) { int tmp = ws[j]; ws[j] = c; c += tmp; }
        }
        __syncthreads();
        int incl = x + ws[w];
        if (t < 196) g_part[t] = incl - v;
        if (t == 0) g_offs[NN] = EE;
        done_inc(C_SC2);
    } else if (b < M_SC3) {
        spin_on(C_SC2, 1);
        int blk = b - M_SC2;
        int i = blk * 256 + t;
        int v = (i < NN) ? (int)g_deg[i] : 0;
        int lane = t & 31, w = t >> 5;
        int x = v;
#pragma unroll
        for (int off = 1; off < 32; off <<= 1) {
            int y = __shfl_up_sync(0xffffffffu, x, off);
            if (lane >= off) x += y;
        }
        __shared__ int ws[8];
        if (lane == 31) ws[w] = x;
        __syncthreads();
        if (t == 0) {
            int c = 0;
#pragma unroll
            for (int j = 0; j < 8; j++) { int tmp = ws[j]; ws[j] = c; c += tmp; }
        }
        __syncthreads();
        int excl = (x - v) + ws[w] + g_part[blk];
        if (i < NN) { g_offs[i] = excl; g_cursor[i] = excl; }
        done_inc(C_SC3);
    } else if (b < M_SCAT) {
        spin_on(C_SC3, 196);
        int gs = b - M_SC3;
        for (int e = gs * 256 + t; e < EE; e += 784 * 256) {
            int r = ei[e];
            int c = ei[EE + e];
            float dc = g_deg[c];
            float dr = g_deg[r];
            float w = ew[e];
            float val = (dr > 0.f) ? w * rsqrtf(dc * dr) : 0.f;
            int slot = atomicAdd(&g_cursor[c], 1);
            g_src[slot] = r;
            g_val[slot] = val;
        }
        // consumed by gather (next launch) — no counter needed
    } else if (b < M_KV) {
        spin_on(C_FIXT, 256);
        spin_on(C_SUMV, 2);
        int wid = (b - M_SCAT) * 8 + (t >> 5);   // 0..16383
        int lane = t & 31;
        int h = wid >> 12, rem = wid & 4095;
        int dd = rem >> 6, m = rem & 63;
        int rk = h * 64 + m, rv = h * 64 + dd;
        const float4* Tp = (const float4*)&g_T[rk * 256];
        const float4* Wp = (const float4*)&Wv[(size_t)rv * CC];
        float4 t0 = Tp[lane], t1 = Tp[lane + 32];
        float4 w0 = Wp[lane], w1 = Wp[lane + 32];
        float acc = t0.x * w0.x + t0.y * w0.y + t0.z * w0.z + t0.w * w0.w
                  + t1.x * w1.x + t1.y * w1.y + t1.z * w1.z + t1.w * w1.w;
#pragma unroll
        for (int off = 16; off > 0; off >>= 1) acc += __shfl_xor_sync(0xffffffffu, acc, off);
        if (lane == 0) {
            float kx = g_ksum[rk] - FNN * bk[rk];
            float vx = g_vsum[rv] - FNN * bv[rv];
            g_kv[h * 4096 + dd * 64 + m] =
                acc + kx * bv[rv] + bk[rk] * vx + FNN * bk[rk] * bv[rv];
        }
        done_inc(C_KV);
    } else if (b < M_KSQ) {
        spin_on(C_FIXT, 256);
        spin_on(C_SUMV, 2);
        int p = b - M_KV;
        float acc = 0.f;
#pragma unroll
        for (int j = 0; j < 4; j++) {
            int idx = p * 1024 + j * 256 + t;
            acc += g_T[idx] * Wk[idx];
        }
#pragma unroll
        for (int off = 16; off > 0; off >>= 1) acc += __shfl_xor_sync(0xffffffffu, acc, off);
        __shared__ float r8[8];
        if ((t & 31) == 0) r8[t >> 5] = acc;
        __syncthreads();
        if (t == 0) {
            float s = 0.f;
#pragma unroll
            for (int j = 0; j < 8; j++) s += r8[j];
            if (p == 0) {
                float e = 0.f;
                for (int i = 0; i < 256; i++) {
                    float kx = g_ksum[i] - FNN * bk[i];
                    e += 2.f * bk[i] * kx + FNN * bk[i] * bk[i];
                }
                s += e;
            }
            atomicAdd(&g_scal[1], s);
        }
        done_inc(C_KSQ);
    } else {
        // attention
        spin_on(C_GEMQ, 782);
        spin_on(C_KV, 2048);
        spin_on(C_KSQ, 64);
        spin_on(C_SUMV, 2);
        attn_body((uint32_t*)smf, b - M_KSQ, out);
    }
}

// ======================== gather launch (atomic-free, full occupancy) ========================
__global__ void gather_kernel(float* __restrict__ out) {
    int t = threadIdx.x;
    int n = blockIdx.x * 4 + (t >> 6);
    int dd = t & 63;
    if (n >= NN) return;
    int e0 = g_offs[n], e1 = g_offs[n + 1];
    float acc = 0.f;
    for (int e = e0; e < e1; ++e) {
        int r = g_src[e];
        float val = g_val[e];
        acc += val * g_vbar[(size_t)r * 64 + dd];
    }
    out[(size_t)n * 64 + dd] += acc;
}

// ---------------- launch ----------------
extern "C" void kernel_launch(void* const* d_in, const int* in_sizes, int n_in,
                              void* d_out, int out_size) {
    const float* query = (const float*)d_in[0];
    const float* source = (const float*)d_in[1];
    const float* Wq = (const float*)d_in[2];
    const float* bq = (const float*)d_in[3];
    const float* Wk = (const float*)d_in[4];
    const float* bk = (const float*)d_in[5];
    const float* Wv = (const float*)d_in[6];
    const float* bv = (const float*)d_in[7];
    const int*   ei = (const int*)d_in[8];
    const float* ew = (const float*)d_in[9];
    float* out = (float*)d_out;

    const int mega_smem = 4 * TSZ * (int)sizeof(float);   // 73728

    cudaFuncSetAttribute(mega, cudaFuncAttributeMaxDynamicSharedMemorySize, mega_smem);

    zero_kernel<<<256, 256>>>(Wv, bv);
    mega<<<M_ATTN, 256, mega_smem>>>(query, Wq, bq, source, Wk, bk, Wv, bv, ei, ew, out);
    gather_kernel<<<12500, 256>>>(out);
}

// round 12
// speedup vs baseline: 1.0936x; 1.0936x over previous
#include <cuda_runtime.h>
#include <cuda_bf16.h>
#include <math.h>
#include <stdint.h>

#define NN 50000
#define CC 256
#define HH 4
#define DD 64
#define EE 800000
#define OC 256   // H*D
#define FNN 50000.0f

// ---------------- device scratch ----------------
__device__ uint32_t g_qb[NN * 128];  // q as packed bf16x2 (col pairs)
__device__ float g_vbar[NN * DD];
__device__ float g_S[OC * OC];       // Xs^T Xs
__device__ float g_T[OC * OC];       // Wk @ S
__device__ float g_xsum[OC];
__device__ float g_wvbar[DD * CC];
__device__ float g_bvbar[DD];
__device__ float g_ksum[OC];
__device__ float g_vsum[OC];
__device__ float g_kv[HH * DD * DD]; // [h][d][m]
__device__ float g_scal[2];
__device__ float g_deg[NN];
__device__ int   g_offs[NN + 1];
__device__ int   g_cursor[NN];
__device__ int   g_src[EE];
__device__ float g_val[EE];
__device__ int   g_part[256];
__device__ int   g_sc1done;

// ---------------- helpers ----------------
__device__ __forceinline__ uint32_t f2tf32(float x) {
    uint32_t r;
    asm("cvt.rna.tf32.f32 %0, %1;" : "=r"(r) : "f"(x));
    return r;
}
__device__ __forceinline__ uint32_t pk(float lo, float hi) {
    uint32_t r;
    asm("cvt.rn.bf16x2.f32 %0, %1, %2;" : "=r"(r) : "f"(hi), "f"(lo));
    return r;
}
__device__ __forceinline__ void mma_tf32(float& d0, float& d1, float& d2, float& d3,
                                         const uint32_t* a, const uint32_t* b) {
    asm volatile(
        "mma.sync.aligned.m16n8k8.row.col.f32.tf32.tf32.f32 "
        "{%0,%1,%2,%3}, {%4,%5,%6,%7}, {%8,%9}, {%0,%1,%2,%3};\n"
        : "+f"(d0), "+f"(d1), "+f"(d2), "+f"(d3)
        : "r"(a[0]), "r"(a[1]), "r"(a[2]), "r"(a[3]), "r"(b[0]), "r"(b[1]));
}
__device__ __forceinline__ void mma_bf16(float& d0, float& d1, float& d2, float& d3,
                                         const uint32_t* a, const uint32_t* b) {
    asm volatile(
        "mma.sync.aligned.m16n8k16.row.col.f32.bf16.bf16.f32 "
        "{%0,%1,%2,%3}, {%4,%5,%6,%7}, {%8,%9}, {%0,%1,%2,%3};\n"
        : "+f"(d0), "+f"(d1), "+f"(d2), "+f"(d3)
        : "r"(a[0]), "r"(a[1]), "r"(a[2]), "r"(a[3]), "r"(b[0]), "r"(b[1]));
}

// ---------------- L1: zero scratch + Wvbar prep ----------------
__global__ void zero_kernel(const float* __restrict__ Wv, const float* __restrict__ bv) {
    int i = blockIdx.x * 256 + threadIdx.x;   // 65536
    g_S[i] = 0.f;
    if (i < NN) g_deg[i] = 0.f;
    if (i < OC) g_xsum[i] = 0.f;
    if (i < 2) g_scal[i] = 0.f;
    if (i == 0) g_sc1done = 0;
    if (i < DD * CC) {
        int d = i >> 8, c = i & 255;
        g_wvbar[i] = 0.25f * (Wv[(d) * CC + c] + Wv[(d + 64) * CC + c] +
                              Wv[(d + 128) * CC + c] + Wv[(d + 192) * CC + c]);
    }
    if (i < DD)
        g_bvbar[i] = 0.25f * (bv[i] + bv[i + 64] + bv[i + 128] + bv[i + 192]);
}

// ======================== phase1 bodies ========================
#define BK 32
#define AST 36
#define TSZ (128 * AST)
#define SST 132
#define CHK 1024
#define NCH 49

// ---- SYRK tile body ----
__device__ void syrk_body(float* smf, int bidx, const float* __restrict__ Xs) {
    float* Ai = smf;
    float* Bj = smf + 2 * 32 * SST;
    int t = threadIdx.x;
    int tile = bidx / NCH;            // 0:(0,0) 1:(0,1) 2:(1,1)
    int chunk = bidx % NCH;
    int ci = (tile == 2) ? 1 : 0;
    int cj = (tile == 0) ? 0 : 1;
    int diag = (ci == cj);
    int nbase = chunk * CHK;
    int lane = t & 31, warp = t >> 5;
    int wm = warp & 1, wn = warp >> 1;

    auto load_tile = [&](int stage, int s) {
#pragma unroll
        for (int p = 0; p < 4; p++) {
            int idx = p * 256 + t;
            int r = idx >> 5;
            int c4 = (idx & 31) * 4;
            int node = nbase + s + r;
            int ok = (node < NN);
            const float* srcA = Xs + (size_t)(ok ? node : 0) * CC + ci * 128 + c4;
            uint32_t da = (uint32_t)__cvta_generic_to_shared(&Ai[stage * 32 * SST + r * SST + c4]);
            int sz = ok ? 16 : 0;
            asm volatile("cp.async.cg.shared.global [%0], [%1], 16, %2;\n"
                         :: "r"(da), "l"(srcA), "r"(sz));
            if (!diag) {
                const float* srcB = Xs + (size_t)(ok ? node : 0) * CC + cj * 128 + c4;
                uint32_t db = (uint32_t)__cvta_generic_to_shared(&Bj[stage * 32 * SST + r * SST + c4]);
                asm volatile("cp.async.cg.shared.global [%0], [%1], 16, %2;\n"
                             :: "r"(db), "l"(srcB), "r"(sz));
            }
        }
        asm volatile("cp.async.commit_group;\n");
    };

    float d[4][4][4];
#pragma unroll
    for (int i = 0; i < 4; i++)
#pragma unroll
        for (int j = 0; j < 4; j++)
#pragma unroll
            for (int c = 0; c < 4; c++) d[i][j][c] = 0.f;

    load_tile(0, 0);
    for (int si = 0; si < CHK / 32; si++) {
        if (si < CHK / 32 - 1) {
            load_tile((si + 1) & 1, (si + 1) * 32);
            asm volatile("cp.async.wait_group 1;\n");
        } else {
            asm volatile("cp.async.wait_group 0;\n");
        }
        __syncthreads();
        const float* Af = Ai + (si & 1) * 32 * SST;
        const float* Bf = diag ? Af : (Bj + (si & 1) * 32 * SST);
#pragma unroll
        for (int kf = 0; kf < 2; kf++) {
            int k = kf * 16 + (lane & 3) * 2;
            uint32_t a[4][4], b[4][2];
#pragma unroll
            for (int mf = 0; mf < 4; mf++) {
                int ra = wm * 64 + mf * 16 + (lane >> 2);
                a[mf][0] = pk(Af[k * SST + ra],       Af[(k + 1) * SST + ra]);
                a[mf][1] = pk(Af[k * SST + ra + 8],   Af[(k + 1) * SST + ra + 8]);
                a[mf][2] = pk(Af[(k + 8) * SST + ra], Af[(k + 9) * SST + ra]);
                a[mf][3] = pk(Af[(k + 8) * SST + ra + 8], Af[(k + 9) * SST + ra + 8]);
            }
#pragma unroll
            for (int nf = 0; nf < 4; nf++) {
                int rb = wn * 32 + nf * 8 + (lane >> 2);
                b[nf][0] = pk(Bf[k * SST + rb],       Bf[(k + 1) * SST + rb]);
                b[nf][1] = pk(Bf[(k + 8) * SST + rb], Bf[(k + 9) * SST + rb]);
            }
#pragma unroll
            for (int nf = 0; nf < 4; nf++)
#pragma unroll
                for (int mf = 0; mf < 4; mf++)
                    mma_bf16(d[mf][nf][0], d[mf][nf][1], d[mf][nf][2], d[mf][nf][3],
                             a[mf], b[nf]);
        }
        __syncthreads();
    }
#pragma unroll
    for (int mf = 0; mf < 4; mf++) {
#pragma unroll
        for (int nf = 0; nf < 4; nf++) {
            int row = ci * 128 + wm * 64 + mf * 16 + (lane >> 2);
            int col = cj * 128 + wn * 32 + nf * 8 + (lane & 3) * 2;
            atomicAdd(&g_S[row * 256 + col],       d[mf][nf][0]);
            atomicAdd(&g_S[row * 256 + col + 1],   d[mf][nf][1]);
            atomicAdd(&g_S[(row + 8) * 256 + col], d[mf][nf][2]);
            atomicAdd(&g_S[(row + 8) * 256 + col + 1], d[mf][nf][3]);
        }
    }
}

// ---- Q GEMM body (bf16, writes packed bf16 q) ----
__device__ void gemmq_body(float* smf, int bi, const float* __restrict__ X,
                           const float* __restrict__ W, const float* __restrict__ B) {
    float* As = smf;
    float* Bs = smf + 2 * TSZ;
    __shared__ float red8[8];

    int t = threadIdx.x;
    int m0 = (bi >> 1) * 128;
    int n0 = (bi & 1) * 128;
    int lane = t & 31, warp = t >> 5;
    int wm = warp & 1, wn = warp >> 1;
    int lr = t >> 3, lc = (t & 7) * 4;

    auto load_tile = [&](int stage, int k0) {
#pragma unroll
        for (int p = 0; p < 4; p++) {
            int r = p * 32 + lr;
            int gr = m0 + r;
            int ok = (gr < NN);
            const float* srcA = X + (size_t)(ok ? gr : 0) * CC + k0 + lc;
            uint32_t da = (uint32_t)__cvta_generic_to_shared(&As[stage * TSZ + r * AST + lc]);
            int szA = ok ? 16 : 0;
            asm volatile("cp.async.cg.shared.global [%0], [%1], 16, %2;\n"
                         :: "r"(da), "l"(srcA), "r"(szA));
            const float* srcB = W + (size_t)(n0 + r) * CC + k0 + lc;
            uint32_t db = (uint32_t)__cvta_generic_to_shared(&Bs[stage * TSZ + r * AST + lc]);
            asm volatile("cp.async.cg.shared.global [%0], [%1], 16;\n"
                         :: "r"(db), "l"(srcB));
        }
        asm volatile("cp.async.commit_group;\n");
    };

    float d[4][4][4];
#pragma unroll
    for (int i = 0; i < 4; i++)
#pragma unroll
        for (int j = 0; j < 4; j++)
#pragma unroll
            for (int c = 0; c < 4; c++) d[i][j][c] = 0.f;

    load_tile(0, 0);
    for (int ki = 0; ki < CC / BK; ki++) {
        if (ki < CC / BK - 1) {
            load_tile((ki + 1) & 1, (ki + 1) * BK);
            asm volatile("cp.async.wait_group 1;\n");
        } else {
            asm volatile("cp.async.wait_group 0;\n");
        }
        __syncthreads();
        const float* Af = As + (ki & 1) * TSZ;
        const float* Bf = Bs + (ki & 1) * TSZ;
#pragma unroll
        for (int kf = 0; kf < 2; kf++) {
            int ka = kf * 16 + (lane & 3) * 2;
            uint32_t a[4][4], b[4][2];
#pragma unroll
            for (int mf = 0; mf < 4; mf++) {
                int ra = wm * 64 + mf * 16 + (lane >> 2);
                float2 x0 = *(const float2*)&Af[ra * AST + ka];
                float2 x1 = *(const float2*)&Af[(ra + 8) * AST + ka];
                float2 x2 = *(const float2*)&Af[ra * AST + ka + 8];
                float2 x3 = *(const float2*)&Af[(ra + 8) * AST + ka + 8];
                a[mf][0] = pk(x0.x, x0.y); a[mf][1] = pk(x1.x, x1.y);
                a[mf][2] = pk(x2.x, x2.y); a[mf][3] = pk(x3.x, x3.y);
            }
#pragma unroll
            for (int nf = 0; nf < 4; nf++) {
                int rb = wn * 32 + nf * 8 + (lane >> 2);
                float2 y0 = *(const float2*)&Bf[rb * AST + ka];
                float2 y1 = *(const float2*)&Bf[rb * AST + ka + 8];
                b[nf][0] = pk(y0.x, y0.y); b[nf][1] = pk(y1.x, y1.y);
            }
#pragma unroll
            for (int nf = 0; nf < 4; nf++)
#pragma unroll
                for (int mf = 0; mf < 4; mf++)
                    mma_bf16(d[mf][nf][0], d[mf][nf][1], d[mf][nf][2], d[mf][nf][3],
                             a[mf], b[nf]);
        }
        __syncthreads();
    }

    float qs = 0.f;
#pragma unroll
    for (int mf = 0; mf < 4; mf++) {
#pragma unroll
        for (int nf = 0; nf < 4; nf++) {
            int row = m0 + wm * 64 + mf * 16 + (lane >> 2);
            int col = n0 + wn * 32 + nf * 8 + (lane & 3) * 2;
            float bi0 = B[col], bi1 = B[col + 1];
            if (row < NN) {
                float o0 = d[mf][nf][0] + bi0, o1 = d[mf][nf][1] + bi1;
                g_qb[(size_t)row * 128 + (col >> 1)] = pk(o0, o1);
                qs += o0 * o0 + o1 * o1;
            }
            if (row + 8 < NN) {
                float o0 = d[mf][nf][2] + bi0, o1 = d[mf][nf][3] + bi1;
                g_qb[(size_t)(row + 8) * 128 + (col >> 1)] = pk(o0, o1);
                qs += o0 * o0 + o1 * o1;
            }
        }
    }
#pragma unroll
    for (int off = 16; off > 0; off >>= 1) qs += __shfl_xor_sync(0xffffffffu, qs, off);
    if (lane == 0) red8[warp] = qs;
    __syncthreads();
    if (t == 0) {
        float s = 0.f;
#pragma unroll
        for (int j = 0; j < 8; j++) s += red8[j];
        atomicAdd(&g_scal[0], s);
    }
}

// ---- vbar GEMM body (tf32) + xsum fold ----
__device__ void vbar_body(float* smf, int bi, const float* __restrict__ Xs) {
    float* As = smf;
    float* Bs = smf + 2 * TSZ;

    int t = threadIdx.x;
    int m0 = bi * 128;
    int lane = t & 31, warp = t >> 5;
    int lr = t >> 3, lc = (t & 7) * 4;

    auto load_tile = [&](int stage, int k0) {
#pragma unroll
        for (int p = 0; p < 4; p++) {
            int r = p * 32 + lr;
            int gr = m0 + r;
            int ok = (gr < NN);
            const float* srcA = Xs + (size_t)(ok ? gr : 0) * CC + k0 + lc;
            uint32_t da = (uint32_t)__cvta_generic_to_shared(&As[stage * TSZ + r * AST + lc]);
            int szA = ok ? 16 : 0;
            asm volatile("cp.async.cg.shared.global [%0], [%1], 16, %2;\n"
                         :: "r"(da), "l"(srcA), "r"(szA));
        }
#pragma unroll
        for (int p = 0; p < 2; p++) {
            int r = p * 32 + lr;
            const float* srcB = g_wvbar + (size_t)r * CC + k0 + lc;
            uint32_t db = (uint32_t)__cvta_generic_to_shared(&Bs[stage * 64 * AST + r * AST + lc]);
            asm volatile("cp.async.cg.shared.global [%0], [%1], 16;\n"
                         :: "r"(db), "l"(srcB));
        }
        asm volatile("cp.async.commit_group;\n");
    };

    float acc[8][4];
#pragma unroll
    for (int i = 0; i < 8; i++)
#pragma unroll
        for (int c = 0; c < 4; c++) acc[i][c] = 0.f;

    load_tile(0, 0);
    for (int ki = 0; ki < CC / BK; ki++) {
        if (ki < CC / BK - 1) {
            load_tile((ki + 1) & 1, (ki + 1) * BK);
            asm volatile("cp.async.wait_group 1;\n");
        } else {
            asm volatile("cp.async.wait_group 0;\n");
        }
        __syncthreads();
        const float* Af = As + (ki & 1) * TSZ;
        const float* Bf = Bs + (ki & 1) * 64 * AST;
        {
            int col = t & 31, rg = t >> 5;
            float p = 0.f;
#pragma unroll
            for (int r = 0; r < 16; r++) p += Af[(rg * 16 + r) * AST + col];
            atomicAdd(&g_xsum[ki * 32 + col], p);
        }
#pragma unroll
        for (int kf = 0; kf < 4; kf++) {
            int ka = kf * 8 + (lane & 3);
            uint32_t a[4];
            int ra = warp * 16 + (lane >> 2);
            a[0] = f2tf32(Af[ra * AST + ka]);
            a[1] = f2tf32(Af[(ra + 8) * AST + ka]);
            a[2] = f2tf32(Af[ra * AST + ka + 4]);
            a[3] = f2tf32(Af[(ra + 8) * AST + ka + 4]);
#pragma unroll
            for (int nf = 0; nf < 8; nf++) {
                int rb = nf * 8 + (lane >> 2);
                uint32_t b[2];
                b[0] = f2tf32(Bf[rb * AST + ka]);
                b[1] = f2tf32(Bf[rb * AST + ka + 4]);
                mma_tf32(acc[nf][0], acc[nf][1], acc[nf][2], acc[nf][3], a, b);
            }
        }
        __syncthreads();
    }
#pragma unroll
    for (int nf = 0; nf < 8; nf++) {
        int row = m0 + warp * 16 + (lane >> 2);
        int col = nf * 8 + (lane & 3) * 2;
        float b0 = g_bvbar[col], b1 = g_bvbar[col + 1];
        if (row < NN)
            *(float2*)&g_vbar[(size_t)row * DD + col] =
                make_float2(acc[nf][0] + b0, acc[nf][1] + b1);
        if (row + 8 < NN)
            *(float2*)&g_vbar[(size_t)(row + 8) * DD + col] =
                make_float2(acc[nf][2] + b0, acc[nf][3] + b1);
    }
}

// ---- phase1 dispatcher: syrk(147) | gemm_q(782) | vbar(391) | degree(391) ----
#define P1_SYRK 147
#define P1_GEMM (P1_SYRK + 782)   // 929
#define P1_VBAR (P1_GEMM + 391)   // 1320
#define P1_TOTAL (P1_VBAR + 391)  // 1711

__global__ void __launch_bounds__(256, 2)
phase1(const float* __restrict__ Xq, const float* __restrict__ Wq, const float* __restrict__ bq,
       const float* __restrict__ Xs, const int* __restrict__ ei)
{
    extern __shared__ float smf[];
    int b = blockIdx.x;
    if (b < P1_SYRK) {
        syrk_body(smf, b, Xs);
    } else if (b < P1_GEMM) {
        gemmq_body(smf, b - P1_SYRK, Xq, Wq, bq);
    } else if (b < P1_VBAR) {
        vbar_body(smf, b - P1_GEMM, Xs);
    } else {
        int gs = b - P1_VBAR;
        for (int e = gs * 256 + threadIdx.x; e < EE; e += 391 * 256)
            atomicAdd(&g_deg[ei[EE + e]], 1.0f);
    }
}

// ======== phase2: fixT(256) | scan1(196) | sumvec(2) | scan2-spin(1) ========
__global__ void phase2(const float* __restrict__ Wk, const float* __restrict__ bk,
                       const float* __restrict__ Wv, const float* __restrict__ bv)
{
    int b = blockIdx.x, t = threadIdx.x;
    if (b < 256) {
        __shared__ float w[256];
        w[t] = Wk[b * CC + t];
        __syncthreads();
        float acc = 0.f;
#pragma unroll 4
        for (int c = 0; c < 256; c++) {
            float s = (c >= 128 && t < 128) ? g_S[t * 256 + c] : g_S[c * 256 + t];
            acc += w[c] * s;
        }
        g_T[b * 256 + t] = acc;
    } else if (b < 452) {
        int blk = b - 256;
        int i = blk * 256 + t;
        int v = (i < NN) ? (int)g_deg[i] : 0;
#pragma unroll
        for (int off = 16; off > 0; off >>= 1) v += __shfl_xor_sync(0xffffffffu, v, off);
        __shared__ int ws[8];
        if ((t & 31) == 0) ws[t >> 5] = v;
        __syncthreads();
        if (t == 0) {
            int s = 0;
#pragma unroll
            for (int j = 0; j < 8; j++) s += ws[j];
            g_part[blk] = s;
            __threadfence();
            atomicAdd(&g_sc1done, 1);
        }
    } else if (b < 454) {
        int sel = b - 452;
        __shared__ float xs[256];
        xs[t] = g_xsum[t];
        __syncthreads();
        const float* W = sel ? Wv : Wk;
        const float* bb = sel ? bv : bk;
        float* dst = sel ? g_vsum : g_ksum;
        float acc = 0.f;
#pragma unroll 4
        for (int c = 0; c < 256; c++) acc += W[t * CC + c] * xs[c];
        dst[t] = acc + FNN * bb[t];
    } else {
        // scan2: spin until all 196 scan1 partials posted, then exclusive-scan them
        if (t == 0) {
            while (atomicAdd(&g_sc1done, 0) < 196) { }
        }
        __syncthreads();
        __threadfence();
        int v = (t < 196) ? g_part[t] : 0;
        int lane = t & 31, w = t >> 5;
        int x = v;
#pragma unroll
        for (int off = 1; off < 32; off <<= 1) {
            int y = __shfl_up_sync(0xffffffffu, x, off);
            if (lane >= off) x += y;
        }
        __shared__ int ws[8];
        if (lane == 31) ws[w] = x;
        __syncthreads();
        if (t == 0) {
            int c = 0;
#pragma unroll
            for (int j = 0; j < 8; j++) { int tmp = ws[j]; ws[j] = c; c += tmp; }
        }
        __syncthreads();
        int incl = x + ws[w];
        if (t < 196) g_part[t] = incl - v;
        if (t == 0) g_offs[NN] = EE;
    }
}

// ======== phase3: kv warp-dot(2048) | ksumsq(64) | scan3(196) ========
#define P3_KV 2048
#define P3_KSQ (P3_KV + 64)      // 2112
#define P3_TOTAL (P3_KSQ + 196)  // 2308

__global__ void phase3(const float* __restrict__ Wk, const float* __restrict__ bk,
                       const float* __restrict__ Wv, const float* __restrict__ bv)
{
    int b = blockIdx.x, t = threadIdx.x;
    if (b < P3_KV) {
        // one warp per kv element, coalesced float4 dot over 256
        int wid = b * 8 + (t >> 5);          // 0..16383
        int lane = t & 31;
        int h = wid >> 12, rem = wid & 4095;
        int dd = rem >> 6, m = rem & 63;
        int rk = h * 64 + m, rv = h * 64 + dd;
        const float4* Tp = (const float4*)&g_T[rk * 256];
        const float4* Wp = (const float4*)&Wv[(size_t)rv * CC];
        float4 t0 = Tp[lane], t1 = Tp[lane + 32];
        float4 w0 = Wp[lane], w1 = Wp[lane + 32];
        float acc = t0.x * w0.x + t0.y * w0.y + t0.z * w0.z + t0.w * w0.w
                  + t1.x * w1.x + t1.y * w1.y + t1.z * w1.z + t1.w * w1.w;
#pragma unroll
        for (int off = 16; off > 0; off >>= 1) acc += __shfl_xor_sync(0xffffffffu, acc, off);
        if (lane == 0) {
            float kx = g_ksum[rk] - FNN * bk[rk];
            float vx = g_vsum[rv] - FNN * bv[rv];
            g_kv[h * 4096 + dd * 64 + m] =
                acc + kx * bv[rv] + bk[rk] * vx + FNN * bk[rk] * bv[rv];
        }
    } else if (b < P3_KSQ) {
        int p = b - P3_KV;
        float acc = 0.f;
#pragma unroll
        for (int j = 0; j < 4; j++) {
            int idx = p * 1024 + j * 256 + t;
            acc += g_T[idx] * Wk[idx];
        }
#pragma unroll
        for (int off = 16; off > 0; off >>= 1) acc += __shfl_xor_sync(0xffffffffu, acc, off);
        __shared__ float r8[8];
        if ((t & 31) == 0) r8[t >> 5] = acc;
        __syncthreads();
        if (t == 0) {
            float s = 0.f;
#pragma unroll
            for (int j = 0; j < 8; j++) s += r8[j];
            if (p == 0) {
                float e = 0.f;
                for (int i = 0; i < 256; i++) {
                    float kx = g_ksum[i] - FNN * bk[i];
                    e += 2.f * bk[i] * kx + FNN * bk[i] * bk[i];
                }
                s += e;
            }
            atomicAdd(&g_scal[1], s);
        }
    } else {
        // scan3
        int blk = b - P3_KSQ;
        int i = blk * 256 + t;
        int v = (i < NN) ? (int)g_deg[i] : 0;
        int lane = t & 31, w = t >> 5;
        int x = v;
#pragma unroll
        for (int off = 1; off < 32; off <<= 1) {
            int y = __shfl_up_sync(0xffffffffu, x, off);
            if (lane >= off) x += y;
        }
        __shared__ int ws[8];
        if (lane == 31) ws[w] = x;
        __syncthreads();
        if (t == 0) {
            int c = 0;
#pragma unroll
            for (int j = 0; j < 8; j++) { int tmp = ws[j]; ws[j] = c; c += tmp; }
        }
        __syncthreads();
        int excl = (x - v) + ws[w] + g_part[blk];
        if (i < NN) { g_offs[i] = excl; g_cursor[i] = excl; }
    }
}

// ======== phase5: attn (bf16 MMA, 391) | scatter (784 grid-stride) ========
#define QSTW 33   // q smem row stride in uint32 words (32 data + 1 pad)
#define KSTW 33
#define P5_ATTN 391
#define P5_TOTAL (P5_ATTN + 784)

__device__ void attn_body(uint32_t* sm, int bi, float* __restrict__ out) {
    uint32_t* sq  = sm;                      // 128 x QSTW (bf16x2 words)
    uint32_t* skv = sm + 128 * QSTW;         // 64 x KSTW
    float* sden = (float*)(skv + 64 * KSTW); // 128
    float* sks  = sden + 128;                // 64
    float* svs  = sks + 64;                  // 64

    int t = threadIdx.x;
    int lane = t & 31, warp = t >> 5;
    int wm = warp >> 1;         // 0..3: 32-row band
    int wn = warp & 1;          // 0..1: 32-col band
    int m0 = bi * 128;
    float scal = rsqrtf(g_scal[0]) * rsqrtf(g_scal[1]);

    float facc[2][4][4];
#pragma unroll
    for (int i = 0; i < 2; i++)
#pragma unroll
        for (int j = 0; j < 4; j++)
#pragma unroll
            for (int c = 0; c < 4; c++) facc[i][j][c] = 0.f;

    for (int h = 0; h < HH; h++) {
        __syncthreads();
        {
            // q tile: 128 rows x 32 words (head h). thread: row = t>>1, half = t&1 (16 words)
            int r = t >> 1, half = (t & 1) * 16;
            int n = m0 + r;
#pragma unroll
            for (int j = 0; j < 4; j++) {
                uint4 u = make_uint4(0u, 0u, 0u, 0u);
                if (n < NN)
                    u = *(const uint4*)&g_qb[(size_t)n * 128 + h * 32 + half + j * 4];
                uint32_t* dst = &sq[r * QSTW + half + j * 4];
                dst[0] = u.x; dst[1] = u.y; dst[2] = u.z; dst[3] = u.w;
            }
            // kv tile: 64 rows x 64 floats -> 32 words. thread: row = t>>2, quarter = t&3
            int kr = t >> 2, kq = (t & 3) * 16;   // 16 floats = 8 words
#pragma unroll
            for (int j = 0; j < 4; j++) {
                float4 v = *(const float4*)&g_kv[h * 4096 + kr * 64 + kq + j * 4];
                uint32_t* dst = &skv[kr * KSTW + (kq >> 1) + j * 2];
                dst[0] = pk(v.x, v.y);
                dst[1] = pk(v.z, v.w);
            }
            if (t < 64) { sks[t] = g_ksum[h * 64 + t]; svs[t] = g_vsum[h * 64 + t]; }
        }
        __syncthreads();
        {
            // denominator per row from bf16 q
            int r = t >> 1, p = t & 1;
            float s = 0.f;
#pragma unroll
            for (int w = 0; w < 16; w++) {
                uint32_t word = sq[r * QSTW + p * 16 + w];
                __nv_bfloat162 bb = *reinterpret_cast<__nv_bfloat162*>(&word);
                s += __bfloat162float(bb.x) * sks[p * 32 + 2 * w]
                   + __bfloat162float(bb.y) * sks[p * 32 + 2 * w + 1];
            }
            s += __shfl_xor_sync(0xffffffffu, s, 1);
            if (p == 0) sden[r] = scal * s + FNN;
        }
        __syncthreads();

        float num[2][4][4];
#pragma unroll
        for (int i = 0; i < 2; i++)
#pragma unroll
            for (int j = 0; j < 4; j++)
#pragma unroll
                for (int c = 0; c < 4; c++) num[i][j][c] = 0.f;

#pragma unroll
        for (int kf = 0; kf < 4; kf++) {          // K=64, 16 per mma
            int kw = kf * 8 + (lane & 3);          // word index of k-pair
            uint32_t a[2][4];
#pragma unroll
            for (int mf = 0; mf < 2; mf++) {
                int ra = wm * 32 + mf * 16 + (lane >> 2);
                a[mf][0] = sq[ra * QSTW + kw];
                a[mf][1] = sq[(ra + 8) * QSTW + kw];
                a[mf][2] = sq[ra * QSTW + kw + 4];
                a[mf][3] = sq[(ra + 8) * QSTW + kw + 4];
            }
#pragma unroll
            for (int nf = 0; nf < 4; nf++) {
                int rb = wn * 32 + nf * 8 + (lane >> 2);
                uint32_t b[2];
                b[0] = skv[rb * KSTW + kw];
                b[1] = skv[rb * KSTW + kw + 4];
#pragma unroll
                for (int mf = 0; mf < 2; mf++)
                    mma_bf16(num[mf][nf][0], num[mf][nf][1], num[mf][nf][2], num[mf][nf][3],
                             a[mf], b);
            }
        }
#pragma unroll
        for (int mf = 0; mf < 2; mf++) {
            int rl = wm * 32 + mf * 16 + (lane >> 2);
            float i0 = 1.f / sden[rl];
            float i1 = 1.f / sden[rl + 8];
#pragma unroll
            for (int nf = 0; nf < 4; nf++) {
                int col = wn * 32 + nf * 8 + (lane & 3) * 2;
                float s0 = svs[col], s1 = svs[col + 1];
                facc[mf][nf][0] += (scal * num[mf][nf][0] + s0) * i0;
                facc[mf][nf][1] += (scal * num[mf][nf][1] + s1) * i0;
                facc[mf][nf][2] += (scal * num[mf][nf][2] + s0) * i1;
                facc[mf][nf][3] += (scal * num[mf][nf][3] + s1) * i1;
            }
        }
    }
#pragma unroll
    for (int mf = 0; mf < 2; mf++) {
#pragma unroll
        for (int nf = 0; nf < 4; nf++) {
            int row = m0 + wm * 32 + mf * 16 + (lane >> 2);
            int col = wn * 32 + nf * 8 + (lane & 3) * 2;
            if (row < NN)
                *(float2*)&out[(size_t)row * 64 + col] =
                    make_float2(0.25f * facc[mf][nf][0], 0.25f * facc[mf][nf][1]);
            if (row + 8 < NN)
                *(float2*)&out[(size_t)(row + 8) * 64 + col] =
                    make_float2(0.25f * facc[mf][nf][2], 0.25f * facc[mf][nf][3]);
        }
    }
}

__global__ void __launch_bounds__(256)
phase5(float* __restrict__ out, const int* __restrict__ ei, const float* __restrict__ ew) {
    extern __shared__ uint32_t smu[];
    int b = blockIdx.x;
    if (b < P5_ATTN) {
        attn_body(smu, b, out);
    } else {
        int gs = b - P5_ATTN;
        for (int e = gs * 256 + threadIdx.x; e < EE; e += 784 * 256) {
            int r = ei[e];
            int c = ei[EE + e];
            float dc = g_deg[c];
            float dr = g_deg[r];
            float w = ew[e];
            float val = (dr > 0.f) ? w * rsqrtf(dc * dr) : 0.f;
            int slot = atomicAdd(&g_cursor[c], 1);
            g_src[slot] = r;
            g_val[slot] = val;
        }
    }
}

// ======== phase6: GCN gather (atomic-free) ========
__global__ void phase6(float* __restrict__ out) {
    int t = threadIdx.x;
    int n = blockIdx.x * 4 + (t >> 6);
    int dd = t & 63;
    if (n >= NN) return;
    int e0 = g_offs[n], e1 = g_offs[n + 1];
    float acc = 0.f;
    for (int e = e0; e < e1; ++e) {
        int r = g_src[e];
        float val = g_val[e];
        acc += val * g_vbar[(size_t)r * 64 + dd];
    }
    out[(size_t)n * 64 + dd] += acc;
}

// ---------------- launch ----------------
extern "C" void kernel_launch(void* const* d_in, const int* in_sizes, int n_in,
                              void* d_out, int out_size) {
    const float* query = (const float*)d_in[0];
    const float* source = (const float*)d_in[1];
    const float* Wq = (const float*)d_in[2];
    const float* bq = (const float*)d_in[3];
    const float* Wk = (const float*)d_in[4];
    const float* bk = (const float*)d_in[5];
    const float* Wv = (const float*)d_in[6];
    const float* bv = (const float*)d_in[7];
    const int*   ei = (const int*)d_in[8];
    const float* ew = (const float*)d_in[9];
    float* out = (float*)d_out;

    const int p1_smem = 4 * TSZ * (int)sizeof(float);                        // 73728
    const int p5_smem = (128 * QSTW + 64 * KSTW) * 4 + (128 + 64 + 64) * 4;  // ~26368

    cudaFuncSetAttribute(phase1, cudaFuncAttributeMaxDynamicSharedMemorySize, p1_smem);
    cudaFuncSetAttribute(phase5, cudaFuncAttributeMaxDynamicSharedMemorySize, p5_smem);

    zero_kernel<<<256, 256>>>(Wv, bv);
    phase1<<<P1_TOTAL, 256, p1_smem>>>(query, Wq, bq, source, ei);
    phase2<<<455, 256>>>(Wk, bk, Wv, bv);
    phase3<<<P3_TOTAL, 256>>>(Wk, bk, Wv, bv);
    phase5<<<P5_TOTAL, 256, p5_smem>>>(out, ei, ew);
    phase6<<<12500, 256>>>(out);
}

// round 13
// speedup vs baseline: 1.0940x; 1.0004x over previous
#include <cuda_runtime.h>
#include <cuda_bf16.h>
#include <math.h>
#include <stdint.h>

#define NN 50000
#define CC 256
#define HH 4
#define DD 64
#define EE 800000
#define OC 256   // H*D
#define FNN 50000.0f

// ---------------- device scratch ----------------
__device__ uint32_t g_qb[NN * 128];  // q as packed bf16x2 (col pairs)
__device__ float g_vbar[NN * DD];
__device__ float g_S[OC * OC];       // Xs^T Xs (FULL matrix: off-diag dual-written)
__device__ float g_T[OC * OC];       // Wk @ S
__device__ float g_xsum[OC];
__device__ float g_wvbar[DD * CC];
__device__ float g_bvbar[DD];
__device__ float g_ksum[OC];
__device__ float g_vsum[OC];
__device__ float g_kv[HH * DD * DD]; // [h][d][m]
__device__ float g_scal[2];
__device__ float g_deg[NN];
__device__ int   g_offs[NN + 1];
__device__ int   g_cursor[NN];
__device__ int   g_src[EE];
__device__ float g_val[EE];
__device__ int   g_part[256];
__device__ int   g_cnt[16];

// dependency counters (used inside `mid` launch only)
#define C_FIXT 0
#define C_SUMV 1
#define C_SC1  2
#define C_SC2  3

__device__ __forceinline__ void done_inc(int idx) {
    __threadfence();
    __syncthreads();
    if (threadIdx.x == 0) atomicAdd(&g_cnt[idx], 1);
}
__device__ __forceinline__ void spin_on(int idx, int target) {
    if (threadIdx.x == 0) {
        while (atomicAdd(&g_cnt[idx], 0) < target) { __nanosleep(64); }
    }
    __syncthreads();
}

// ---------------- helpers ----------------
__device__ __forceinline__ uint32_t f2tf32(float x) {
    uint32_t r;
    asm("cvt.rna.tf32.f32 %0, %1;" : "=r"(r) : "f"(x));
    return r;
}
__device__ __forceinline__ uint32_t pk(float lo, float hi) {
    uint32_t r;
    asm("cvt.rn.bf16x2.f32 %0, %1, %2;" : "=r"(r) : "f"(hi), "f"(lo));
    return r;
}
__device__ __forceinline__ void mma_tf32(float& d0, float& d1, float& d2, float& d3,
                                         const uint32_t* a, const uint32_t* b) {
    asm volatile(
        "mma.sync.aligned.m16n8k8.row.col.f32.tf32.tf32.f32 "
        "{%0,%1,%2,%3}, {%4,%5,%6,%7}, {%8,%9}, {%0,%1,%2,%3};\n"
        : "+f"(d0), "+f"(d1), "+f"(d2), "+f"(d3)
        : "r"(a[0]), "r"(a[1]), "r"(a[2]), "r"(a[3]), "r"(b[0]), "r"(b[1]));
}
__device__ __forceinline__ void mma_bf16(float& d0, float& d1, float& d2, float& d3,
                                         const uint32_t* a, const uint32_t* b) {
    asm volatile(
        "mma.sync.aligned.m16n8k16.row.col.f32.bf16.bf16.f32 "
        "{%0,%1,%2,%3}, {%4,%5,%6,%7}, {%8,%9}, {%0,%1,%2,%3};\n"
        : "+f"(d0), "+f"(d1), "+f"(d2), "+f"(d3)
        : "r"(a[0]), "r"(a[1]), "r"(a[2]), "r"(a[3]), "r"(b[0]), "r"(b[1]));
}

// ---------------- L1: zero scratch + counters + Wvbar prep ----------------
__global__ void zero_kernel(const float* __restrict__ Wv, const float* __restrict__ bv) {
    int i = blockIdx.x * 256 + threadIdx.x;   // 65536
    g_S[i] = 0.f;
    if (i < NN) g_deg[i] = 0.f;
    if (i < OC) g_xsum[i] = 0.f;
    if (i < 2) g_scal[i] = 0.f;
    if (i < 16) g_cnt[i] = 0;
    if (i < DD * CC) {
        int d = i >> 8, c = i & 255;
        g_wvbar[i] = 0.25f * (Wv[(d) * CC + c] + Wv[(d + 64) * CC + c] +
                              Wv[(d + 128) * CC + c] + Wv[(d + 192) * CC + c]);
    }
    if (i < DD)
        g_bvbar[i] = 0.25f * (bv[i] + bv[i + 64] + bv[i + 128] + bv[i + 192]);
}

// ======================== phase1 bodies ========================
#define BK 32
#define AST 36
#define TSZ (128 * AST)
#define SST 132
#define CHK 1024
#define NCH 49

// ---- SYRK tile body (off-diag also writes transposed tile -> S is FULL) ----
__device__ void syrk_body(float* smf, int bidx, const float* __restrict__ Xs) {
    float* Ai = smf;
    float* Bj = smf + 2 * 32 * SST;
    int t = threadIdx.x;
    int tile = bidx / NCH;            // 0:(0,0) 1:(0,1) 2:(1,1)
    int chunk = bidx % NCH;
    int ci = (tile == 2) ? 1 : 0;
    int cj = (tile == 0) ? 0 : 1;
    int diag = (ci == cj);
    int nbase = chunk * CHK;
    int lane = t & 31, warp = t >> 5;
    int wm = warp & 1, wn = warp >> 1;

    auto load_tile = [&](int stage, int s) {
#pragma unroll
        for (int p = 0; p < 4; p++) {
            int idx = p * 256 + t;
            int r = idx >> 5;
            int c4 = (idx & 31) * 4;
            int node = nbase + s + r;
            int ok = (node < NN);
            const float* srcA = Xs + (size_t)(ok ? node : 0) * CC + ci * 128 + c4;
            uint32_t da = (uint32_t)__cvta_generic_to_shared(&Ai[stage * 32 * SST + r * SST + c4]);
            int sz = ok ? 16 : 0;
            asm volatile("cp.async.cg.shared.global [%0], [%1], 16, %2;\n"
                         :: "r"(da), "l"(srcA), "r"(sz));
            if (!diag) {
                const float* srcB = Xs + (size_t)(ok ? node : 0) * CC + cj * 128 + c4;
                uint32_t db = (uint32_t)__cvta_generic_to_shared(&Bj[stage * 32 * SST + r * SST + c4]);
                asm volatile("cp.async.cg.shared.global [%0], [%1], 16, %2;\n"
                             :: "r"(db), "l"(srcB), "r"(sz));
            }
        }
        asm volatile("cp.async.commit_group;\n");
    };

    float d[4][4][4];
#pragma unroll
    for (int i = 0; i < 4; i++)
#pragma unroll
        for (int j = 0; j < 4; j++)
#pragma unroll
            for (int c = 0; c < 4; c++) d[i][j][c] = 0.f;

    load_tile(0, 0);
    for (int si = 0; si < CHK / 32; si++) {
        if (si < CHK / 32 - 1) {
            load_tile((si + 1) & 1, (si + 1) * 32);
            asm volatile("cp.async.wait_group 1;\n");
        } else {
            asm volatile("cp.async.wait_group 0;\n");
        }
        __syncthreads();
        const float* Af = Ai + (si & 1) * 32 * SST;
        const float* Bf = diag ? Af : (Bj + (si & 1) * 32 * SST);
#pragma unroll
        for (int kf = 0; kf < 2; kf++) {
            int k = kf * 16 + (lane & 3) * 2;
            uint32_t a[4][4], b[4][2];
#pragma unroll
            for (int mf = 0; mf < 4; mf++) {
                int ra = wm * 64 + mf * 16 + (lane >> 2);
                a[mf][0] = pk(Af[k * SST + ra],       Af[(k + 1) * SST + ra]);
                a[mf][1] = pk(Af[k * SST + ra + 8],   Af[(k + 1) * SST + ra + 8]);
                a[mf][2] = pk(Af[(k + 8) * SST + ra], Af[(k + 9) * SST + ra]);
                a[mf][3] = pk(Af[(k + 8) * SST + ra + 8], Af[(k + 9) * SST + ra + 8]);
            }
#pragma unroll
            for (int nf = 0; nf < 4; nf++) {
                int rb = wn * 32 + nf * 8 + (lane >> 2);
                b[nf][0] = pk(Bf[k * SST + rb],       Bf[(k + 1) * SST + rb]);
                b[nf][1] = pk(Bf[(k + 8) * SST + rb], Bf[(k + 9) * SST + rb]);
            }
#pragma unroll
            for (int nf = 0; nf < 4; nf++)
#pragma unroll
                for (int mf = 0; mf < 4; mf++)
                    mma_bf16(d[mf][nf][0], d[mf][nf][1], d[mf][nf][2], d[mf][nf][3],
                             a[mf], b[nf]);
        }
        __syncthreads();
    }
#pragma unroll
    for (int mf = 0; mf < 4; mf++) {
#pragma unroll
        for (int nf = 0; nf < 4; nf++) {
            int row = ci * 128 + wm * 64 + mf * 16 + (lane >> 2);
            int col = cj * 128 + wn * 32 + nf * 8 + (lane & 3) * 2;
            atomicAdd(&g_S[row * 256 + col],       d[mf][nf][0]);
            atomicAdd(&g_S[row * 256 + col + 1],   d[mf][nf][1]);
            atomicAdd(&g_S[(row + 8) * 256 + col], d[mf][nf][2]);
            atomicAdd(&g_S[(row + 8) * 256 + col + 1], d[mf][nf][3]);
            if (!diag) {   // dual-write transposed tile so S is full
                atomicAdd(&g_S[col * 256 + row],           d[mf][nf][0]);
                atomicAdd(&g_S[(col + 1) * 256 + row],     d[mf][nf][1]);
                atomicAdd(&g_S[col * 256 + row + 8],       d[mf][nf][2]);
                atomicAdd(&g_S[(col + 1) * 256 + row + 8], d[mf][nf][3]);
            }
        }
    }
}

// ---- Q GEMM body (bf16, writes packed bf16 q) ----
__device__ void gemmq_body(float* smf, int bi, const float* __restrict__ X,
                           const float* __restrict__ W, const float* __restrict__ B) {
    float* As = smf;
    float* Bs = smf + 2 * TSZ;
    __shared__ float red8[8];

    int t = threadIdx.x;
    int m0 = (bi >> 1) * 128;
    int n0 = (bi & 1) * 128;
    int lane = t & 31, warp = t >> 5;
    int wm = warp & 1, wn = warp >> 1;
    int lr = t >> 3, lc = (t & 7) * 4;

    auto load_tile = [&](int stage, int k0) {
#pragma unroll
        for (int p = 0; p < 4; p++) {
            int r = p * 32 + lr;
            int gr = m0 + r;
            int ok = (gr < NN);
            const float* srcA = X + (size_t)(ok ? gr : 0) * CC + k0 + lc;
            uint32_t da = (uint32_t)__cvta_generic_to_shared(&As[stage * TSZ + r * AST + lc]);
            int szA = ok ? 16 : 0;
            asm volatile("cp.async.cg.shared.global [%0], [%1], 16, %2;\n"
                         :: "r"(da), "l"(srcA), "r"(szA));
            const float* srcB = W + (size_t)(n0 + r) * CC + k0 + lc;
            uint32_t db = (uint32_t)__cvta_generic_to_shared(&Bs[stage * TSZ + r * AST + lc]);
            asm volatile("cp.async.cg.shared.global [%0], [%1], 16;\n"
                         :: "r"(db), "l"(srcB));
        }
        asm volatile("cp.async.commit_group;\n");
    };

    float d[4][4][4];
#pragma unroll
    for (int i = 0; i < 4; i++)
#pragma unroll
        for (int j = 0; j < 4; j++)
#pragma unroll
            for (int c = 0; c < 4; c++) d[i][j][c] = 0.f;

    load_tile(0, 0);
    for (int ki = 0; ki < CC / BK; ki++) {
        if (ki < CC / BK - 1) {
            load_tile((ki + 1) & 1, (ki + 1) * BK);
            asm volatile("cp.async.wait_group 1;\n");
        } else {
            asm volatile("cp.async.wait_group 0;\n");
        }
        __syncthreads();
        const float* Af = As + (ki & 1) * TSZ;
        const float* Bf = Bs + (ki & 1) * TSZ;
#pragma unroll
        for (int kf = 0; kf < 2; kf++) {
            int ka = kf * 16 + (lane & 3) * 2;
            uint32_t a[4][4], b[4][2];
#pragma unroll
            for (int mf = 0; mf < 4; mf++) {
                int ra = wm * 64 + mf * 16 + (lane >> 2);
                float2 x0 = *(const float2*)&Af[ra * AST + ka];
                float2 x1 = *(const float2*)&Af[(ra + 8) * AST + ka];
                float2 x2 = *(const float2*)&Af[ra * AST + ka + 8];
                float2 x3 = *(const float2*)&Af[(ra + 8) * AST + ka + 8];
                a[mf][0] = pk(x0.x, x0.y); a[mf][1] = pk(x1.x, x1.y);
                a[mf][2] = pk(x2.x, x2.y); a[mf][3] = pk(x3.x, x3.y);
            }
#pragma unroll
            for (int nf = 0; nf < 4; nf++) {
                int rb = wn * 32 + nf * 8 + (lane >> 2);
                float2 y0 = *(const float2*)&Bf[rb * AST + ka];
                float2 y1 = *(const float2*)&Bf[rb * AST + ka + 8];
                b[nf][0] = pk(y0.x, y0.y); b[nf][1] = pk(y1.x, y1.y);
            }
#pragma unroll
            for (int nf = 0; nf < 4; nf++)
#pragma unroll
                for (int mf = 0; mf < 4; mf++)
                    mma_bf16(d[mf][nf][0], d[mf][nf][1], d[mf][nf][2], d[mf][nf][3],
                             a[mf], b[nf]);
        }
        __syncthreads();
    }

    float qs = 0.f;
#pragma unroll
    for (int mf = 0; mf < 4; mf++) {
#pragma unroll
        for (int nf = 0; nf < 4; nf++) {
            int row = m0 + wm * 64 + mf * 16 + (lane >> 2);
            int col = n0 + wn * 32 + nf * 8 + (lane & 3) * 2;
            float bi0 = B[col], bi1 = B[col + 1];
            if (row < NN) {
                float o0 = d[mf][nf][0] + bi0, o1 = d[mf][nf][1] + bi1;
                g_qb[(size_t)row * 128 + (col >> 1)] = pk(o0, o1);
                qs += o0 * o0 + o1 * o1;
            }
            if (row + 8 < NN) {
                float o0 = d[mf][nf][2] + bi0, o1 = d[mf][nf][3] + bi1;
                g_qb[(size_t)(row + 8) * 128 + (col >> 1)] = pk(o0, o1);
                qs += o0 * o0 + o1 * o1;
            }
        }
    }
#pragma unroll
    for (int off = 16; off > 0; off >>= 1) qs += __shfl_xor_sync(0xffffffffu, qs, off);
    if (lane == 0) red8[warp] = qs;
    __syncthreads();
    if (t == 0) {
        float s = 0.f;
#pragma unroll
        for (int j = 0; j < 8; j++) s += red8[j];
        atomicAdd(&g_scal[0], s);
    }
}

// ---- vbar GEMM body (tf32) + xsum fold ----
__device__ void vbar_body(float* smf, int bi, const float* __restrict__ Xs) {
    float* As = smf;
    float* Bs = smf + 2 * TSZ;

    int t = threadIdx.x;
    int m0 = bi * 128;
    int lane = t & 31, warp = t >> 5;
    int lr = t >> 3, lc = (t & 7) * 4;

    auto load_tile = [&](int stage, int k0) {
#pragma unroll
        for (int p = 0; p < 4; p++) {
            int r = p * 32 + lr;
            int gr = m0 + r;
            int ok = (gr < NN);
            const float* srcA = Xs + (size_t)(ok ? gr : 0) * CC + k0 + lc;
            uint32_t da = (uint32_t)__cvta_generic_to_shared(&As[stage * TSZ + r * AST + lc]);
            int szA = ok ? 16 : 0;
            asm volatile("cp.async.cg.shared.global [%0], [%1], 16, %2;\n"
                         :: "r"(da), "l"(srcA), "r"(szA));
        }
#pragma unroll
        for (int p = 0; p < 2; p++) {
            int r = p * 32 + lr;
            const float* srcB = g_wvbar + (size_t)r * CC + k0 + lc;
            uint32_t db = (uint32_t)__cvta_generic_to_shared(&Bs[stage * 64 * AST + r * AST + lc]);
            asm volatile("cp.async.cg.shared.global [%0], [%1], 16;\n"
                         :: "r"(db), "l"(srcB));
        }
        asm volatile("cp.async.commit_group;\n");
    };

    float acc[8][4];
#pragma unroll
    for (int i = 0; i < 8; i++)
#pragma unroll
        for (int c = 0; c < 4; c++) acc[i][c] = 0.f;

    load_tile(0, 0);
    for (int ki = 0; ki < CC / BK; ki++) {
        if (ki < CC / BK - 1) {
            load_tile((ki + 1) & 1, (ki + 1) * BK);
            asm volatile("cp.async.wait_group 1;\n");
        } else {
            asm volatile("cp.async.wait_group 0;\n");
        }
        __syncthreads();
        const float* Af = As + (ki & 1) * TSZ;
        const float* Bf = Bs + (ki & 1) * 64 * AST;
        {
            int col = t & 31, rg = t >> 5;
            float p = 0.f;
#pragma unroll
            for (int r = 0; r < 16; r++) p += Af[(rg * 16 + r) * AST + col];
            atomicAdd(&g_xsum[ki * 32 + col], p);
        }
#pragma unroll
        for (int kf = 0; kf < 4; kf++) {
            int ka = kf * 8 + (lane & 3);
            uint32_t a[4];
            int ra = warp * 16 + (lane >> 2);
            a[0] = f2tf32(Af[ra * AST + ka]);
            a[1] = f2tf32(Af[(ra + 8) * AST + ka]);
            a[2] = f2tf32(Af[ra * AST + ka + 4]);
            a[3] = f2tf32(Af[(ra + 8) * AST + ka + 4]);
#pragma unroll
            for (int nf = 0; nf < 8; nf++) {
                int rb = nf * 8 + (lane >> 2);
                uint32_t b[2];
                b[0] = f2tf32(Bf[rb * AST + ka]);
                b[1] = f2tf32(Bf[rb * AST + ka + 4]);
                mma_tf32(acc[nf][0], acc[nf][1], acc[nf][2], acc[nf][3], a, b);
            }
        }
        __syncthreads();
    }
#pragma unroll
    for (int nf = 0; nf < 8; nf++) {
        int row = m0 + warp * 16 + (lane >> 2);
        int col = nf * 8 + (lane & 3) * 2;
        float b0 = g_bvbar[col], b1 = g_bvbar[col + 1];
        if (row < NN)
            *(float2*)&g_vbar[(size_t)row * DD + col] =
                make_float2(acc[nf][0] + b0, acc[nf][1] + b1);
        if (row + 8 < NN)
            *(float2*)&g_vbar[(size_t)(row + 8) * DD + col] =
                make_float2(acc[nf][2] + b0, acc[nf][3] + b1);
    }
}

// ---- phase1 dispatcher: syrk(147) | gemm_q(782) | vbar(391) | degree(391) ----
#define P1_SYRK 147
#define P1_GEMM (P1_SYRK + 782)   // 929
#define P1_VBAR (P1_GEMM + 391)   // 1320
#define P1_TOTAL (P1_VBAR + 391)  // 1711

__global__ void __launch_bounds__(256, 2)
phase1(const float* __restrict__ Xq, const float* __restrict__ Wq, const float* __restrict__ bq,
       const float* __restrict__ Xs, const int* __restrict__ ei)
{
    extern __shared__ float smf[];
    int b = blockIdx.x;
    if (b < P1_SYRK) {
        syrk_body(smf, b, Xs);
    } else if (b < P1_GEMM) {
        gemmq_body(smf, b - P1_SYRK, Xq, Wq, bq);
    } else if (b < P1_VBAR) {
        vbar_body(smf, b - P1_GEMM, Xs);
    } else {
        int gs = b - P1_VBAR;
        for (int e = gs * 256 + threadIdx.x; e < EE; e += 391 * 256)
            atomicAdd(&g_deg[ei[EE + e]], 1.0f);
    }
}

// ======== mid: fixT(256)|scan1(196)|sumvec(2)|scan2(1)|kv(2048)|ksq(64)|scan3(196) ========
// All bodies <=32 regs, ~1KB smem -> 8 blocks/SM. Producers (bids 0..454) always in wave 1;
// waiter classes (kv 2048, ksq 64, scan3 196) spin only on wave-1 producers, and can never
// fill all slots while a producer is undispatched -> deadlock-free.
#define MD_FIXT 256
#define MD_SC1  (MD_FIXT + 196)  // 452
#define MD_SUMV (MD_SC1 + 2)     // 454
#define MD_SC2  (MD_SUMV + 1)    // 455
#define MD_KV   (MD_SC2 + 2048)  // 2503
#define MD_KSQ  (MD_KV + 64)     // 2567
#define MD_TOTAL (MD_KSQ + 196)  // 2763

__global__ void __launch_bounds__(256)
mid(const float* __restrict__ Wk, const float* __restrict__ bk,
    const float* __restrict__ Wv, const float* __restrict__ bv)
{
    int b = blockIdx.x, t = threadIdx.x;
    if (b < MD_FIXT) {
        // fixT: T = Wk @ S (S full -> coalesced reads)
        __shared__ float w[256];
        w[t] = Wk[b * CC + t];
        __syncthreads();
        float acc = 0.f;
#pragma unroll 4
        for (int c = 0; c < 256; c++)
            acc += w[c] * g_S[c * 256 + t];
        g_T[b * 256 + t] = acc;
        done_inc(C_FIXT);
    } else if (b < MD_SC1) {
        int blk = b - MD_FIXT;
        int i = blk * 256 + t;
        int v = (i < NN) ? (int)g_deg[i] : 0;
#pragma unroll
        for (int off = 16; off > 0; off >>= 1) v += __shfl_xor_sync(0xffffffffu, v, off);
        __shared__ int ws[8];
        if ((t & 31) == 0) ws[t >> 5] = v;
        __syncthreads();
        if (t == 0) {
            int s = 0;
#pragma unroll
            for (int j = 0; j < 8; j++) s += ws[j];
            g_part[blk] = s;
        }
        done_inc(C_SC1);
    } else if (b < MD_SUMV) {
        int sel = b - MD_SC1;
        __shared__ float xs[256];
        xs[t] = g_xsum[t];
        __syncthreads();
        const float* W = sel ? Wv : Wk;
        const float* bb = sel ? bv : bk;
        float* dst = sel ? g_vsum : g_ksum;
        float acc = 0.f;
#pragma unroll 4
        for (int c = 0; c < 256; c++) acc += W[t * CC + c] * xs[c];
        dst[t] = acc + FNN * bb[t];
        done_inc(C_SUMV);
    } else if (b < MD_SC2) {
        spin_on(C_SC1, 196);
        int v = (t < 196) ? g_part[t] : 0;
        int lane = t & 31, w = t >> 5;
        int x = v;
#pragma unroll
        for (int off = 1; off < 32; off <<= 1) {
            int y = __shfl_up_sync(0xffffffffu, x, off);
            if (lane >= off) x += y;
        }
        __shared__ int ws[8];
        if (lane == 31) ws[w] = x;
        __syncthreads();
        if (t == 0) {
            int c = 0;
#pragma unroll
            for (int j = 0; j < 8; j++) { int tmp = ws[j]; ws[j] = c; c += tmp; }
        }
        __syncthreads();
        int incl = x + ws[w];
        if (t < 196) g_part[t] = incl - v;
        if (t == 0) g_offs[NN] = EE;
        done_inc(C_SC2);
    } else if (b < MD_KV) {
        spin_on(C_FIXT, 256);
        spin_on(C_SUMV, 2);
        // one warp per kv element, coalesced float4 dot over 256
        int wid = (b - MD_SC2) * 8 + (t >> 5);   // 0..16383
        int lane = t & 31;
        int h = wid >> 12, rem = wid & 4095;
        int dd = rem >> 6, m = rem & 63;
        int rk = h * 64 + m, rv = h * 64 + dd;
        const float4* Tp = (const float4*)&g_T[rk * 256];
        const float4* Wp = (const float4*)&Wv[(size_t)rv * CC];
        float4 t0 = Tp[lane], t1 = Tp[lane + 32];
        float4 w0 = Wp[lane], w1 = Wp[lane + 32];
        float acc = t0.x * w0.x + t0.y * w0.y + t0.z * w0.z + t0.w * w0.w
                  + t1.x * w1.x + t1.y * w1.y + t1.z * w1.z + t1.w * w1.w;
#pragma unroll
        for (int off = 16; off > 0; off >>= 1) acc += __shfl_xor_sync(0xffffffffu, acc, off);
        if (lane == 0) {
            float kx = g_ksum[rk] - FNN * bk[rk];
            float vx = g_vsum[rv] - FNN * bv[rv];
            g_kv[h * 4096 + dd * 64 + m] =
                acc + kx * bv[rv] + bk[rk] * vx + FNN * bk[rk] * bv[rv];
        }
    } else if (b < MD_KSQ) {
        spin_on(C_FIXT, 256);
        spin_on(C_SUMV, 2);
        int p = b - MD_KV;
        float acc = 0.f;
#pragma unroll
        for (int j = 0; j < 4; j++) {
            int idx = p * 1024 + j * 256 + t;
            acc += g_T[idx] * Wk[idx];
        }
#pragma unroll
        for (int off = 16; off > 0; off >>= 1) acc += __shfl_xor_sync(0xffffffffu, acc, off);
        __shared__ float r8[8];
        if ((t & 31) == 0) r8[t >> 5] = acc;
        __syncthreads();
        if (t == 0) {
            float s = 0.f;
#pragma unroll
            for (int j = 0; j < 8; j++) s += r8[j];
            if (p == 0) {
                float e = 0.f;
                for (int i = 0; i < 256; i++) {
                    float kx = g_ksum[i] - FNN * bk[i];
                    e += 2.f * bk[i] * kx + FNN * bk[i] * bk[i];
                }
                s += e;
            }
            atomicAdd(&g_scal[1], s);
        }
    } else {
        // scan3
        spin_on(C_SC2, 1);
        int blk = b - MD_KSQ;
        int i = blk * 256 + t;
        int v = (i < NN) ? (int)g_deg[i] : 0;
        int lane = t & 31, w = t >> 5;
        int x = v;
#pragma unroll
        for (int off = 1; off < 32; off <<= 1) {
            int y = __shfl_up_sync(0xffffffffu, x, off);
            if (lane >= off) x += y;
        }
        __shared__ int ws[8];
        if (lane == 31) ws[w] = x;
        __syncthreads();
        if (t == 0) {
            int c = 0;
#pragma unroll
            for (int j = 0; j < 8; j++) { int tmp = ws[j]; ws[j] = c; c += tmp; }
        }
        __syncthreads();
        int excl = (x - v) + ws[w] + g_part[blk];
        if (i < NN) { g_offs[i] = excl; g_cursor[i] = excl; }
    }
}

// ======== phase5: attn (bf16 MMA, 391) | scatter (784 grid-stride) ========
#define QSTW 33   // q smem row stride in uint32 words (32 data + 1 pad)
#define KSTW 33
#define P5_ATTN 391
#define P5_TOTAL (P5_ATTN + 784)

__device__ void attn_body(uint32_t* sm, int bi, float* __restrict__ out) {
    uint32_t* sq  = sm;                      // 128 x QSTW (bf16x2 words)
    uint32_t* skv = sm + 128 * QSTW;         // 64 x KSTW
    float* sden = (float*)(skv + 64 * KSTW); // 128
    float* sks  = sden + 128;                // 64
    float* svs  = sks + 64;                  // 64

    int t = threadIdx.x;
    int lane = t & 31, warp = t >> 5;
    int wm = warp >> 1;         // 0..3: 32-row band
    int wn = warp & 1;          // 0..1: 32-col band
    int m0 = bi * 128;
    float scal = rsqrtf(g_scal[0]) * rsqrtf(g_scal[1]);

    float facc[2][4][4];
#pragma unroll
    for (int i = 0; i < 2; i++)
#pragma unroll
        for (int j = 0; j < 4; j++)
#pragma unroll
            for (int c = 0; c < 4; c++) facc[i][j][c] = 0.f;

    for (int h = 0; h < HH; h++) {
        __syncthreads();
        {
            int r = t >> 1, half = (t & 1) * 16;
            int n = m0 + r;
#pragma unroll
            for (int j = 0; j < 4; j++) {
                uint4 u = make_uint4(0u, 0u, 0u, 0u);
                if (n < NN)
                    u = *(const uint4*)&g_qb[(size_t)n * 128 + h * 32 + half + j * 4];
                uint32_t* dst = &sq[r * QSTW + half + j * 4];
                dst[0] = u.x; dst[1] = u.y; dst[2] = u.z; dst[3] = u.w;
            }
            int kr = t >> 2, kq = (t & 3) * 16;
#pragma unroll
            for (int j = 0; j < 4; j++) {
                float4 v = *(const float4*)&g_kv[h * 4096 + kr * 64 + kq + j * 4];
                uint32_t* dst = &skv[kr * KSTW + (kq >> 1) + j * 2];
                dst[0] = pk(v.x, v.y);
                dst[1] = pk(v.z, v.w);
            }
            if (t < 64) { sks[t] = g_ksum[h * 64 + t]; svs[t] = g_vsum[h * 64 + t]; }
        }
        __syncthreads();
        {
            int r = t >> 1, p = t & 1;
            float s = 0.f;
#pragma unroll
            for (int w = 0; w < 16; w++) {
                uint32_t word = sq[r * QSTW + p * 16 + w];
                __nv_bfloat162 bb = *reinterpret_cast<__nv_bfloat162*>(&word);
                s += __bfloat162float(bb.x) * sks[p * 32 + 2 * w]
                   + __bfloat162float(bb.y) * sks[p * 32 + 2 * w + 1];
            }
            s += __shfl_xor_sync(0xffffffffu, s, 1);
            if (p == 0) sden[r] = scal * s + FNN;
        }
        __syncthreads();

        float num[2][4][4];
#pragma unroll
        for (int i = 0; i < 2; i++)
#pragma unroll
            for (int j = 0; j < 4; j++)
#pragma unroll
                for (int c = 0; c < 4; c++) num[i][j][c] = 0.f;

#pragma unroll
        for (int kf = 0; kf < 4; kf++) {          // K=64, 16 per mma
            int kw = kf * 8 + (lane & 3);
            uint32_t a[2][4];
#pragma unroll
            for (int mf = 0; mf < 2; mf++) {
                int ra = wm * 32 + mf * 16 + (lane >> 2);
                a[mf][0] = sq[ra * QSTW + kw];
                a[mf][1] = sq[(ra + 8) * QSTW + kw];
                a[mf][2] = sq[ra * QSTW + kw + 4];
                a[mf][3] = sq[(ra + 8) * QSTW + kw + 4];
            }
#pragma unroll
            for (int nf = 0; nf < 4; nf++) {
                int rb = wn * 32 + nf * 8 + (lane >> 2);
                uint32_t b[2];
                b[0] = skv[rb * KSTW + kw];
                b[1] = skv[rb * KSTW + kw + 4];
#pragma unroll
                for (int mf = 0; mf < 2; mf++)
                    mma_bf16(num[mf][nf][0], num[mf][nf][1], num[mf][nf][2], num[mf][nf][3],
                             a[mf], b);
            }
        }
#pragma unroll
        for (int mf = 0; mf < 2; mf++) {
            int rl = wm * 32 + mf * 16 + (lane >> 2);
            float i0 = 1.f / sden[rl];
            float i1 = 1.f / sden[rl + 8];
#pragma unroll
            for (int nf = 0; nf < 4; nf++) {
                int col = wn * 32 + nf * 8 + (lane & 3) * 2;
                float s0 = svs[col], s1 = svs[col + 1];
                facc[mf][nf][0] += (scal * num[mf][nf][0] + s0) * i0;
                facc[mf][nf][1] += (scal * num[mf][nf][1] + s1) * i0;
                facc[mf][nf][2] += (scal * num[mf][nf][2] + s0) * i1;
                facc[mf][nf][3] += (scal * num[mf][nf][3] + s1) * i1;
            }
        }
    }
#pragma unroll
    for (int mf = 0; mf < 2; mf++) {
#pragma unroll
        for (int nf = 0; nf < 4; nf++) {
            int row = m0 + wm * 32 + mf * 16 + (lane >> 2);
            int col = wn * 32 + nf * 8 + (lane & 3) * 2;
            if (row < NN)
                *(float2*)&out[(size_t)row * 64 + col] =
                    make_float2(0.25f * facc[mf][nf][0], 0.25f * facc[mf][nf][1]);
            if (row + 8 < NN)
                *(float2*)&out[(size_t)(row + 8) * 64 + col] =
                    make_float2(0.25f * facc[mf][nf][2], 0.25f * facc[mf][nf][3]);
        }
    }
}

__global__ void __launch_bounds__(256)
phase5(float* __restrict__ out, const int* __restrict__ ei, const float* __restrict__ ew) {
    extern __shared__ uint32_t smu[];
    int b = blockIdx.x;
    if (b < P5_ATTN) {
        attn_body(smu, b, out);
    } else {
        int gs = b - P5_ATTN;
        for (int e = gs * 256 + threadIdx.x; e < EE; e += 784 * 256) {
            int r = ei[e];
            int c = ei[EE + e];
            float dc = g_deg[c];
            float dr = g_deg[r];
            float w = ew[e];
            float val = (dr > 0.f) ? w * rsqrtf(dc * dr) : 0.f;
            int slot = atomicAdd(&g_cursor[c], 1);
            g_src[slot] = r;
            g_val[slot] = val;
        }
    }
}

// ======== phase6: GCN gather (atomic-free) ========
__global__ void phase6(float* __restrict__ out) {
    int t = threadIdx.x;
    int n = blockIdx.x * 4 + (t >> 6);
    int dd = t & 63;
    if (n >= NN) return;
    int e0 = g_offs[n], e1 = g_offs[n + 1];
    float acc = 0.f;
    for (int e = e0; e < e1; ++e) {
        int r = g_src[e];
        float val = g_val[e];
        acc += val * g_vbar[(size_t)r * 64 + dd];
    }
    out[(size_t)n * 64 + dd] += acc;
}

// ---------------- launch ----------------
extern "C" void kernel_launch(void* const* d_in, const int* in_sizes, int n_in,
                              void* d_out, int out_size) {
    const float* query = (const float*)d_in[0];
    const float* source = (const float*)d_in[1];
    const float* Wq = (const float*)d_in[2];
    const float* bq = (const float*)d_in[3];
    const float* Wk = (const float*)d_in[4];
    const float* bk = (const float*)d_in[5];
    const float* Wv = (const float*)d_in[6];
    const float* bv = (const float*)d_in[7];
    const int*   ei = (const int*)d_in[8];
    const float* ew = (const float*)d_in[9];
    float* out = (float*)d_out;

    const int p1_smem = 4 * TSZ * (int)sizeof(float);                        // 73728
    const int p5_smem = (128 * QSTW + 64 * KSTW) * 4 + (128 + 64 + 64) * 4;  // ~26368

    cudaFuncSetAttribute(phase1, cudaFuncAttributeMaxDynamicSharedMemorySize, p1_smem);
    cudaFuncSetAttribute(phase5, cudaFuncAttributeMaxDynamicSharedMemorySize, p5_smem);

    zero_kernel<<<256, 256>>>(Wv, bv);
    phase1<<<P1_TOTAL, 256, p1_smem>>>(query, Wq, bq, source, ei);
    mid<<<MD_TOTAL, 256>>>(Wk, bk, Wv, bv);
    phase5<<<P5_TOTAL, 256, p5_smem>>>(out, ei, ew);
    phase6<<<12500, 256>>>(out);
}

// round 14
// speedup vs baseline: 1.1147x; 1.0189x over previous
#include <cuda_runtime.h>
#include <cuda_bf16.h>
#include <math.h>
#include <stdint.h>

#define NN 50000
#define CC 256
#define HH 4
#define DD 64
#define EE 800000
#define OC 256   // H*D
#define FNN 50000.0f

// ---------------- device scratch ----------------
__device__ uint32_t g_qb[NN * 128];  // q as packed bf16x2 (col pairs)
__device__ float g_vbar[NN * DD];
__device__ float g_S[OC * OC];       // Xs^T Xs (FULL matrix: off-diag dual-written)
__device__ float g_T[OC * OC];       // Wk @ S
__device__ float g_xsum[OC];
__device__ float g_wvbar[DD * CC];
__device__ float g_bvbar[DD];
__device__ float g_ksum[OC];
__device__ float g_vsum[OC];
__device__ float g_kv[HH * DD * DD]; // [h][d][m]
__device__ float g_scal[2];
__device__ float g_deg[NN];
__device__ int   g_offs[NN + 1];
__device__ int   g_cursor[NN];
__device__ int   g_src[EE];
__device__ float g_val[EE];
__device__ int   g_part[256];
__device__ int   g_cnt[16];

// dependency counters (used inside `mid` launch only)
#define C_FIXT 0
#define C_SUMV 1
#define C_SC1  2
#define C_SC2  3

__device__ __forceinline__ void done_inc(int idx) {
    __threadfence();
    __syncthreads();
    if (threadIdx.x == 0) atomicAdd(&g_cnt[idx], 1);
}
__device__ __forceinline__ void spin_on(int idx, int target) {
    if (threadIdx.x == 0) {
        while (atomicAdd(&g_cnt[idx], 0) < target) { __nanosleep(64); }
    }
    __syncthreads();
}

// ---------------- helpers ----------------
__device__ __forceinline__ uint32_t f2tf32(float x) {
    uint32_t r;
    asm("cvt.rna.tf32.f32 %0, %1;" : "=r"(r) : "f"(x));
    return r;
}
__device__ __forceinline__ uint32_t pk(float lo, float hi) {
    uint32_t r;
    asm("cvt.rn.bf16x2.f32 %0, %1, %2;" : "=r"(r) : "f"(hi), "f"(lo));
    return r;
}
__device__ __forceinline__ void mma_tf32(float& d0, float& d1, float& d2, float& d3,
                                         const uint32_t* a, const uint32_t* b) {
    asm volatile(
        "mma.sync.aligned.m16n8k8.row.col.f32.tf32.tf32.f32 "
        "{%0,%1,%2,%3}, {%4,%5,%6,%7}, {%8,%9}, {%0,%1,%2,%3};\n"
        : "+f"(d0), "+f"(d1), "+f"(d2), "+f"(d3)
        : "r"(a[0]), "r"(a[1]), "r"(a[2]), "r"(a[3]), "r"(b[0]), "r"(b[1]));
}
__device__ __forceinline__ void mma_bf16(float& d0, float& d1, float& d2, float& d3,
                                         const uint32_t* a, const uint32_t* b) {
    asm volatile(
        "mma.sync.aligned.m16n8k16.row.col.f32.bf16.bf16.f32 "
        "{%0,%1,%2,%3}, {%4,%5,%6,%7}, {%8,%9}, {%0,%1,%2,%3};\n"
        : "+f"(d0), "+f"(d1), "+f"(d2), "+f"(d3)
        : "r"(a[0]), "r"(a[1]), "r"(a[2]), "r"(a[3]), "r"(b[0]), "r"(b[1]));
}

// ---------------- L1: zero scratch + counters + Wvbar prep ----------------
__global__ void zero_kernel(const float* __restrict__ Wv, const float* __restrict__ bv) {
    int i = blockIdx.x * 256 + threadIdx.x;   // 65536
    g_S[i] = 0.f;
    if (i < NN) g_deg[i] = 0.f;
    if (i < OC) g_xsum[i] = 0.f;
    if (i < 2) g_scal[i] = 0.f;
    if (i < 16) g_cnt[i] = 0;
    if (i < DD * CC) {
        int d = i >> 8, c = i & 255;
        g_wvbar[i] = 0.25f * (Wv[(d) * CC + c] + Wv[(d + 64) * CC + c] +
                              Wv[(d + 128) * CC + c] + Wv[(d + 192) * CC + c]);
    }
    if (i < DD)
        g_bvbar[i] = 0.25f * (bv[i] + bv[i + 64] + bv[i + 128] + bv[i + 192]);
}

// ======================== phase1 bodies ========================
#define BK 32
#define AST 36
#define TSZ (128 * AST)
#define SST 132
#define CHK 1024
#define NCH 49

// ---- SYRK tile body (off-diag also writes transposed tile -> S is FULL) ----
__device__ void syrk_body(float* smf, int bidx, const float* __restrict__ Xs) {
    float* Ai = smf;
    float* Bj = smf + 2 * 32 * SST;
    int t = threadIdx.x;
    int tile = bidx / NCH;            // 0:(0,0) 1:(0,1) 2:(1,1)
    int chunk = bidx % NCH;
    int ci = (tile == 2) ? 1 : 0;
    int cj = (tile == 0) ? 0 : 1;
    int diag = (ci == cj);
    int nbase = chunk * CHK;
    int lane = t & 31, warp = t >> 5;
    int wm = warp & 1, wn = warp >> 1;

    auto load_tile = [&](int stage, int s) {
#pragma unroll
        for (int p = 0; p < 4; p++) {
            int idx = p * 256 + t;
            int r = idx >> 5;
            int c4 = (idx & 31) * 4;
            int node = nbase + s + r;
            int ok = (node < NN);
            const float* srcA = Xs + (size_t)(ok ? node : 0) * CC + ci * 128 + c4;
            uint32_t da = (uint32_t)__cvta_generic_to_shared(&Ai[stage * 32 * SST + r * SST + c4]);
            int sz = ok ? 16 : 0;
            asm volatile("cp.async.cg.shared.global [%0], [%1], 16, %2;\n"
                         :: "r"(da), "l"(srcA), "r"(sz));
            if (!diag) {
                const float* srcB = Xs + (size_t)(ok ? node : 0) * CC + cj * 128 + c4;
                uint32_t db = (uint32_t)__cvta_generic_to_shared(&Bj[stage * 32 * SST + r * SST + c4]);
                asm volatile("cp.async.cg.shared.global [%0], [%1], 16, %2;\n"
                             :: "r"(db), "l"(srcB), "r"(sz));
            }
        }
        asm volatile("cp.async.commit_group;\n");
    };

    float d[4][4][4];
#pragma unroll
    for (int i = 0; i < 4; i++)
#pragma unroll
        for (int j = 0; j < 4; j++)
#pragma unroll
            for (int c = 0; c < 4; c++) d[i][j][c] = 0.f;

    load_tile(0, 0);
    for (int si = 0; si < CHK / 32; si++) {
        if (si < CHK / 32 - 1) {
            load_tile((si + 1) & 1, (si + 1) * 32);
            asm volatile("cp.async.wait_group 1;\n");
        } else {
            asm volatile("cp.async.wait_group 0;\n");
        }
        __syncthreads();
        const float* Af = Ai + (si & 1) * 32 * SST;
        const float* Bf = diag ? Af : (Bj + (si & 1) * 32 * SST);
#pragma unroll
        for (int kf = 0; kf < 2; kf++) {
            int k = kf * 16 + (lane & 3) * 2;
            uint32_t a[4][4], b[4][2];
#pragma unroll
            for (int mf = 0; mf < 4; mf++) {
                int ra = wm * 64 + mf * 16 + (lane >> 2);
                a[mf][0] = pk(Af[k * SST + ra],       Af[(k + 1) * SST + ra]);
                a[mf][1] = pk(Af[k * SST + ra + 8],   Af[(k + 1) * SST + ra + 8]);
                a[mf][2] = pk(Af[(k + 8) * SST + ra], Af[(k + 9) * SST + ra]);
                a[mf][3] = pk(Af[(k + 8) * SST + ra + 8], Af[(k + 9) * SST + ra + 8]);
            }
#pragma unroll
            for (int nf = 0; nf < 4; nf++) {
                int rb = wn * 32 + nf * 8 + (lane >> 2);
                b[nf][0] = pk(Bf[k * SST + rb],       Bf[(k + 1) * SST + rb]);
                b[nf][1] = pk(Bf[(k + 8) * SST + rb], Bf[(k + 9) * SST + rb]);
            }
#pragma unroll
            for (int nf = 0; nf < 4; nf++)
#pragma unroll
                for (int mf = 0; mf < 4; mf++)
                    mma_bf16(d[mf][nf][0], d[mf][nf][1], d[mf][nf][2], d[mf][nf][3],
                             a[mf], b[nf]);
        }
        __syncthreads();
    }
#pragma unroll
    for (int mf = 0; mf < 4; mf++) {
#pragma unroll
        for (int nf = 0; nf < 4; nf++) {
            int row = ci * 128 + wm * 64 + mf * 16 + (lane >> 2);
            int col = cj * 128 + wn * 32 + nf * 8 + (lane & 3) * 2;
            atomicAdd(&g_S[row * 256 + col],       d[mf][nf][0]);
            atomicAdd(&g_S[row * 256 + col + 1],   d[mf][nf][1]);
            atomicAdd(&g_S[(row + 8) * 256 + col], d[mf][nf][2]);
            atomicAdd(&g_S[(row + 8) * 256 + col + 1], d[mf][nf][3]);
            if (!diag) {   // dual-write transposed tile so S is full
                atomicAdd(&g_S[col * 256 + row],           d[mf][nf][0]);
                atomicAdd(&g_S[(col + 1) * 256 + row],     d[mf][nf][1]);
                atomicAdd(&g_S[col * 256 + row + 8],       d[mf][nf][2]);
                atomicAdd(&g_S[(col + 1) * 256 + row + 8], d[mf][nf][3]);
            }
        }
    }
}

// ---- Q GEMM body (bf16, writes packed bf16 q) ----
__device__ void gemmq_body(float* smf, int bi, const float* __restrict__ X,
                           const float* __restrict__ W, const float* __restrict__ B) {
    float* As = smf;
    float* Bs = smf + 2 * TSZ;
    __shared__ float red8[8];

    int t = threadIdx.x;
    int m0 = (bi >> 1) * 128;
    int n0 = (bi & 1) * 128;
    int lane = t & 31, warp = t >> 5;
    int wm = warp & 1, wn = warp >> 1;
    int lr = t >> 3, lc = (t & 7) * 4;

    auto load_tile = [&](int stage, int k0) {
#pragma unroll
        for (int p = 0; p < 4; p++) {
            int r = p * 32 + lr;
            int gr = m0 + r;
            int ok = (gr < NN);
            const float* srcA = X + (size_t)(ok ? gr : 0) * CC + k0 + lc;
            uint32_t da = (uint32_t)__cvta_generic_to_shared(&As[stage * TSZ + r * AST + lc]);
            int szA = ok ? 16 : 0;
            asm volatile("cp.async.cg.shared.global [%0], [%1], 16, %2;\n"
                         :: "r"(da), "l"(srcA), "r"(szA));
            const float* srcB = W + (size_t)(n0 + r) * CC + k0 + lc;
            uint32_t db = (uint32_t)__cvta_generic_to_shared(&Bs[stage * TSZ + r * AST + lc]);
            asm volatile("cp.async.cg.shared.global [%0], [%1], 16;\n"
                         :: "r"(db), "l"(srcB));
        }
        asm volatile("cp.async.commit_group;\n");
    };

    float d[4][4][4];
#pragma unroll
    for (int i = 0; i < 4; i++)
#pragma unroll
        for (int j = 0; j < 4; j++)
#pragma unroll
            for (int c = 0; c < 4; c++) d[i][j][c] = 0.f;

    load_tile(0, 0);
    for (int ki = 0; ki < CC / BK; ki++) {
        if (ki < CC / BK - 1) {
            load_tile((ki + 1) & 1, (ki + 1) * BK);
            asm volatile("cp.async.wait_group 1;\n");
        } else {
            asm volatile("cp.async.wait_group 0;\n");
        }
        __syncthreads();
        const float* Af = As + (ki & 1) * TSZ;
        const float* Bf = Bs + (ki & 1) * TSZ;
#pragma unroll
        for (int kf = 0; kf < 2; kf++) {
            int ka = kf * 16 + (lane & 3) * 2;
            uint32_t a[4][4], b[4][2];
#pragma unroll
            for (int mf = 0; mf < 4; mf++) {
                int ra = wm * 64 + mf * 16 + (lane >> 2);
                float2 x0 = *(const float2*)&Af[ra * AST + ka];
                float2 x1 = *(const float2*)&Af[(ra + 8) * AST + ka];
                float2 x2 = *(const float2*)&Af[ra * AST + ka + 8];
                float2 x3 = *(const float2*)&Af[(ra + 8) * AST + ka + 8];
                a[mf][0] = pk(x0.x, x0.y); a[mf][1] = pk(x1.x, x1.y);
                a[mf][2] = pk(x2.x, x2.y); a[mf][3] = pk(x3.x, x3.y);
            }
#pragma unroll
            for (int nf = 0; nf < 4; nf++) {
                int rb = wn * 32 + nf * 8 + (lane >> 2);
                float2 y0 = *(const float2*)&Bf[rb * AST + ka];
                float2 y1 = *(const float2*)&Bf[rb * AST + ka + 8];
                b[nf][0] = pk(y0.x, y0.y); b[nf][1] = pk(y1.x, y1.y);
            }
#pragma unroll
            for (int nf = 0; nf < 4; nf++)
#pragma unroll
                for (int mf = 0; mf < 4; mf++)
                    mma_bf16(d[mf][nf][0], d[mf][nf][1], d[mf][nf][2], d[mf][nf][3],
                             a[mf], b[nf]);
        }
        __syncthreads();
    }

    float qs = 0.f;
#pragma unroll
    for (int mf = 0; mf < 4; mf++) {
#pragma unroll
        for (int nf = 0; nf < 4; nf++) {
            int row = m0 + wm * 64 + mf * 16 + (lane >> 2);
            int col = n0 + wn * 32 + nf * 8 + (lane & 3) * 2;
            float bi0 = B[col], bi1 = B[col + 1];
            if (row < NN) {
                float o0 = d[mf][nf][0] + bi0, o1 = d[mf][nf][1] + bi1;
                g_qb[(size_t)row * 128 + (col >> 1)] = pk(o0, o1);
                qs += o0 * o0 + o1 * o1;
            }
            if (row + 8 < NN) {
                float o0 = d[mf][nf][2] + bi0, o1 = d[mf][nf][3] + bi1;
                g_qb[(size_t)(row + 8) * 128 + (col >> 1)] = pk(o0, o1);
                qs += o0 * o0 + o1 * o1;
            }
        }
    }
#pragma unroll
    for (int off = 16; off > 0; off >>= 1) qs += __shfl_xor_sync(0xffffffffu, qs, off);
    if (lane == 0) red8[warp] = qs;
    __syncthreads();
    if (t == 0) {
        float s = 0.f;
#pragma unroll
        for (int j = 0; j < 8; j++) s += red8[j];
        atomicAdd(&g_scal[0], s);
    }
}

// ---- vbar GEMM body (tf32) + xsum fold ----
__device__ void vbar_body(float* smf, int bi, const float* __restrict__ Xs) {
    float* As = smf;
    float* Bs = smf + 2 * TSZ;

    int t = threadIdx.x;
    int m0 = bi * 128;
    int lane = t & 31, warp = t >> 5;
    int lr = t >> 3, lc = (t & 7) * 4;

    auto load_tile = [&](int stage, int k0) {
#pragma unroll
        for (int p = 0; p < 4; p++) {
            int r = p * 32 + lr;
            int gr = m0 + r;
            int ok = (gr < NN);
            const float* srcA = Xs + (size_t)(ok ? gr : 0) * CC + k0 + lc;
            uint32_t da = (uint32_t)__cvta_generic_to_shared(&As[stage * TSZ + r * AST + lc]);
            int szA = ok ? 16 : 0;
            asm volatile("cp.async.cg.shared.global [%0], [%1], 16, %2;\n"
                         :: "r"(da), "l"(srcA), "r"(szA));
        }
#pragma unroll
        for (int p = 0; p < 2; p++) {
            int r = p * 32 + lr;
            const float* srcB = g_wvbar + (size_t)r * CC + k0 + lc;
            uint32_t db = (uint32_t)__cvta_generic_to_shared(&Bs[stage * 64 * AST + r * AST + lc]);
            asm volatile("cp.async.cg.shared.global [%0], [%1], 16;\n"
                         :: "r"(db), "l"(srcB));
        }
        asm volatile("cp.async.commit_group;\n");
    };

    float acc[8][4];
#pragma unroll
    for (int i = 0; i < 8; i++)
#pragma unroll
        for (int c = 0; c < 4; c++) acc[i][c] = 0.f;

    load_tile(0, 0);
    for (int ki = 0; ki < CC / BK; ki++) {
        if (ki < CC / BK - 1) {
            load_tile((ki + 1) & 1, (ki + 1) * BK);
            asm volatile("cp.async.wait_group 1;\n");
        } else {
            asm volatile("cp.async.wait_group 0;\n");
        }
        __syncthreads();
        const float* Af = As + (ki & 1) * TSZ;
        const float* Bf = Bs + (ki & 1) * 64 * AST;
        {
            int col = t & 31, rg = t >> 5;
            float p = 0.f;
#pragma unroll
            for (int r = 0; r < 16; r++) p += Af[(rg * 16 + r) * AST + col];
            atomicAdd(&g_xsum[ki * 32 + col], p);
        }
#pragma unroll
        for (int kf = 0; kf < 4; kf++) {
            int ka = kf * 8 + (lane & 3);
            uint32_t a[4];
            int ra = warp * 16 + (lane >> 2);
            a[0] = f2tf32(Af[ra * AST + ka]);
            a[1] = f2tf32(Af[(ra + 8) * AST + ka]);
            a[2] = f2tf32(Af[ra * AST + ka + 4]);
            a[3] = f2tf32(Af[(ra + 8) * AST + ka + 4]);
#pragma unroll
            for (int nf = 0; nf < 8; nf++) {
                int rb = nf * 8 + (lane >> 2);
                uint32_t b[2];
                b[0] = f2tf32(Bf[rb * AST + ka]);
                b[1] = f2tf32(Bf[rb * AST + ka + 4]);
                mma_tf32(acc[nf][0], acc[nf][1], acc[nf][2], acc[nf][3], a, b);
            }
        }
        __syncthreads();
    }
#pragma unroll
    for (int nf = 0; nf < 8; nf++) {
        int row = m0 + warp * 16 + (lane >> 2);
        int col = nf * 8 + (lane & 3) * 2;
        float b0 = g_bvbar[col], b1 = g_bvbar[col + 1];
        if (row < NN)
            *(float2*)&g_vbar[(size_t)row * DD + col] =
                make_float2(acc[nf][0] + b0, acc[nf][1] + b1);
        if (row + 8 < NN)
            *(float2*)&g_vbar[(size_t)(row + 8) * DD + col] =
                make_float2(acc[nf][2] + b0, acc[nf][3] + b1);
    }
}

// ---- phase1 dispatcher: syrk(147) | gemm_q(782) | vbar(391) | degree(391) ----
#define P1_SYRK 147
#define P1_GEMM (P1_SYRK + 782)   // 929
#define P1_VBAR (P1_GEMM + 391)   // 1320
#define P1_TOTAL (P1_VBAR + 391)  // 1711

__global__ void __launch_bounds__(256, 2)
phase1(const float* __restrict__ Xq, const float* __restrict__ Wq, const float* __restrict__ bq,
       const float* __restrict__ Xs, const int* __restrict__ ei)
{
    extern __shared__ float smf[];
    int b = blockIdx.x;
    if (b < P1_SYRK) {
        syrk_body(smf, b, Xs);
    } else if (b < P1_GEMM) {
        gemmq_body(smf, b - P1_SYRK, Xq, Wq, bq);
    } else if (b < P1_VBAR) {
        vbar_body(smf, b - P1_GEMM, Xs);
    } else {
        int gs = b - P1_VBAR;
        for (int e = gs * 256 + threadIdx.x; e < EE; e += 391 * 256)
            atomicAdd(&g_deg[ei[EE + e]], 1.0f);
    }
}

// ======== mid: fixT|scan1|sumvec|scan2|kv|ksq|scan3|vb2 ========
#define MD_FIXT 256
#define MD_SC1  (MD_FIXT + 196)  // 452
#define MD_SUMV (MD_SC1 + 2)     // 454
#define MD_SC2  (MD_SUMV + 1)    // 455
#define MD_KV   (MD_SC2 + 2048)  // 2503
#define MD_KSQ  (MD_KV + 64)     // 2567
#define MD_SC3  (MD_KSQ + 196)   // 2763
#define MD_VB2G 784
#define MD_TOTAL (MD_SC3 + MD_VB2G)  // 3547

__global__ void __launch_bounds__(256)
mid(const float* __restrict__ Wk, const float* __restrict__ bk,
    const float* __restrict__ Wv, const float* __restrict__ bv)
{
    int b = blockIdx.x, t = threadIdx.x;
    if (b < MD_FIXT) {
        // fixT: T = Wk @ S (S full -> coalesced reads)
        __shared__ float w[256];
        w[t] = Wk[b * CC + t];
        __syncthreads();
        float acc = 0.f;
#pragma unroll 4
        for (int c = 0; c < 256; c++)
            acc += w[c] * g_S[c * 256 + t];
        g_T[b * 256 + t] = acc;
        done_inc(C_FIXT);
    } else if (b < MD_SC1) {
        int blk = b - MD_FIXT;
        int i = blk * 256 + t;
        int v = (i < NN) ? (int)g_deg[i] : 0;
#pragma unroll
        for (int off = 16; off > 0; off >>= 1) v += __shfl_xor_sync(0xffffffffu, v, off);
        __shared__ int ws[8];
        if ((t & 31) == 0) ws[t >> 5] = v;
        __syncthreads();
        if (t == 0) {
            int s = 0;
#pragma unroll
            for (int j = 0; j < 8; j++) s += ws[j];
            g_part[blk] = s;
        }
        done_inc(C_SC1);
    } else if (b < MD_SUMV) {
        int sel = b - MD_SC1;
        __shared__ float xs[256];
        xs[t] = g_xsum[t];
        __syncthreads();
        const float* W = sel ? Wv : Wk;
        const float* bb = sel ? bv : bk;
        float* dst = sel ? g_vsum : g_ksum;
        float acc = 0.f;
#pragma unroll 4
        for (int c = 0; c < 256; c++) acc += W[t * CC + c] * xs[c];
        dst[t] = acc + FNN * bb[t];
        done_inc(C_SUMV);
    } else if (b < MD_SC2) {
        spin_on(C_SC1, 196);
        int v = (t < 196) ? g_part[t] : 0;
        int lane = t & 31, w = t >> 5;
        int x = v;
#pragma unroll
        for (int off = 1; off < 32; off <<= 1) {
            int y = __shfl_up_sync(0xffffffffu, x, off);
            if (lane >= off) x += y;
        }
        __shared__ int ws[8];
        if (lane == 31) ws[w] = x;
        __syncthreads();
        if (t == 0) {
            int c = 0;
#pragma unroll
            for (int j = 0; j < 8; j++) { int tmp = ws[j]; ws[j] = c; c += tmp; }
        }
        __syncthreads();
        int incl = x + ws[w];
        if (t < 196) g_part[t] = incl - v;
        if (t == 0) g_offs[NN] = EE;
        done_inc(C_SC2);
    } else if (b < MD_KV) {
        spin_on(C_FIXT, 256);
        spin_on(C_SUMV, 2);
        // one warp per kv element, coalesced float4 dot over 256
        int wid = (b - MD_SC2) * 8 + (t >> 5);   // 0..16383
        int lane = t & 31;
        int h = wid >> 12, rem = wid & 4095;
        int dd = rem >> 6, m = rem & 63;
        int rk = h * 64 + m, rv = h * 64 + dd;
        const float4* Tp = (const float4*)&g_T[rk * 256];
        const float4* Wp = (const float4*)&Wv[(size_t)rv * CC];
        float4 t0 = Tp[lane], t1 = Tp[lane + 32];
        float4 w0 = Wp[lane], w1 = Wp[lane + 32];
        float acc = t0.x * w0.x + t0.y * w0.y + t0.z * w0.z + t0.w * w0.w
                  + t1.x * w1.x + t1.y * w1.y + t1.z * w1.z + t1.w * w1.w;
#pragma unroll
        for (int off = 16; off > 0; off >>= 1) acc += __shfl_xor_sync(0xffffffffu, acc, off);
        if (lane == 0) {
            float kx = g_ksum[rk] - FNN * bk[rk];
            float vx = g_vsum[rv] - FNN * bv[rv];
            g_kv[h * 4096 + dd * 64 + m] =
                acc + kx * bv[rv] + bk[rk] * vx + FNN * bk[rk] * bv[rv];
        }
    } else if (b < MD_KSQ) {
        spin_on(C_FIXT, 256);
        spin_on(C_SUMV, 2);
        int p = b - MD_KV;
        float acc = 0.f;
#pragma unroll
        for (int j = 0; j < 4; j++) {
            int idx = p * 1024 + j * 256 + t;
            acc += g_T[idx] * Wk[idx];
        }
#pragma unroll
        for (int off = 16; off > 0; off >>= 1) acc += __shfl_xor_sync(0xffffffffu, acc, off);
        __shared__ float r8[8];
        if ((t & 31) == 0) r8[t >> 5] = acc;
        __syncthreads();
        if (t == 0) {
            float s = 0.f;
#pragma unroll
            for (int j = 0; j < 8; j++) s += r8[j];
            if (p == 0) {
                float e = 0.f;
                for (int i = 0; i < 256; i++) {
                    float kx = g_ksum[i] - FNN * bk[i];
                    e += 2.f * bk[i] * kx + FNN * bk[i] * bk[i];
                }
                s += e;
            }
            atomicAdd(&g_scal[1], s);
        }
    } else if (b < MD_SC3) {
        // scan3
        spin_on(C_SC2, 1);
        int blk = b - MD_KSQ;
        int i = blk * 256 + t;
        int v = (i < NN) ? (int)g_deg[i] : 0;
        int lane = t & 31, w = t >> 5;
        int x = v;
#pragma unroll
        for (int off = 1; off < 32; off <<= 1) {
            int y = __shfl_up_sync(0xffffffffu, x, off);
            if (lane >= off) x += y;
        }
        __shared__ int ws[8];
        if (lane == 31) ws[w] = x;
        __syncthreads();
        if (t == 0) {
            int c = 0;
#pragma unroll
            for (int j = 0; j < 8; j++) { int tmp = ws[j]; ws[j] = c; c += tmp; }
        }
        __syncthreads();
        int excl = (x - v) + ws[w] + g_part[blk];
        if (i < NN) { g_offs[i] = excl; g_cursor[i] = excl; }
    } else {
        // vb2: vbar[n] *= (deg[n]>0 ? rsqrt(deg[n]) : 0)  — deg & vbar ready pre-launch
        int gs = b - MD_SC3;
        const int TOT = NN * 16;   // float4 units
        for (int i = gs * 256 + t; i < TOT; i += MD_VB2G * 256) {
            int n = i >> 4;
            float dg = g_deg[n];
            float sc = (dg > 0.f) ? rsqrtf(dg) : 0.f;
            float4* p = (float4*)&g_vbar[(size_t)i * 4];
            float4 v = *p;
            v.x *= sc; v.y *= sc; v.z *= sc; v.w *= sc;
            *p = v;
        }
    }
}

// ======== phase5: attn (bf16 MMA, 391) | scatter (784 grid-stride) ========
#define QSTW 33   // q smem row stride in uint32 words (32 data + 1 pad)
#define KSTW 33
#define P5_ATTN 391
#define P5_TOTAL (P5_ATTN + 784)

__device__ void attn_body(uint32_t* sm, int bi, float* __restrict__ out) {
    uint32_t* sq  = sm;                      // 128 x QSTW (bf16x2 words)
    uint32_t* skv = sm + 128 * QSTW;         // 64 x KSTW
    float* sden = (float*)(skv + 64 * KSTW); // 128
    float* sks  = sden + 128;                // 64
    float* svs  = sks + 64;                  // 64

    int t = threadIdx.x;
    int lane = t & 31, warp = t >> 5;
    int wm = warp >> 1;         // 0..3: 32-row band
    int wn = warp & 1;          // 0..1: 32-col band
    int m0 = bi * 128;
    float scal = rsqrtf(g_scal[0]) * rsqrtf(g_scal[1]);

    float facc[2][4][4];
#pragma unroll
    for (int i = 0; i < 2; i++)
#pragma unroll
        for (int j = 0; j < 4; j++)
#pragma unroll
            for (int c = 0; c < 4; c++) facc[i][j][c] = 0.f;

    for (int h = 0; h < HH; h++) {
        __syncthreads();
        {
            int r = t >> 1, half = (t & 1) * 16;
            int n = m0 + r;
#pragma unroll
            for (int j = 0; j < 4; j++) {
                uint4 u = make_uint4(0u, 0u, 0u, 0u);
                if (n < NN)
                    u = *(const uint4*)&g_qb[(size_t)n * 128 + h * 32 + half + j * 4];
                uint32_t* dst = &sq[r * QSTW + half + j * 4];
                dst[0] = u.x; dst[1] = u.y; dst[2] = u.z; dst[3] = u.w;
            }
            int kr = t >> 2, kq = (t & 3) * 16;
#pragma unroll
            for (int j = 0; j < 4; j++) {
                float4 v = *(const float4*)&g_kv[h * 4096 + kr * 64 + kq + j * 4];
                uint32_t* dst = &skv[kr * KSTW + (kq >> 1) + j * 2];
                dst[0] = pk(v.x, v.y);
                dst[1] = pk(v.z, v.w);
            }
            if (t < 64) { sks[t] = g_ksum[h * 64 + t]; svs[t] = g_vsum[h * 64 + t]; }
        }
        __syncthreads();
        {
            int r = t >> 1, p = t & 1;
            float s = 0.f;
#pragma unroll
            for (int w = 0; w < 16; w++) {
                uint32_t word = sq[r * QSTW + p * 16 + w];
                __nv_bfloat162 bb = *reinterpret_cast<__nv_bfloat162*>(&word);
                s += __bfloat162float(bb.x) * sks[p * 32 + 2 * w]
                   + __bfloat162float(bb.y) * sks[p * 32 + 2 * w + 1];
            }
            s += __shfl_xor_sync(0xffffffffu, s, 1);
            if (p == 0) sden[r] = scal * s + FNN;
        }
        __syncthreads();

        float num[2][4][4];
#pragma unroll
        for (int i = 0; i < 2; i++)
#pragma unroll
            for (int j = 0; j < 4; j++)
#pragma unroll
                for (int c = 0; c < 4; c++) num[i][j][c] = 0.f;

#pragma unroll
        for (int kf = 0; kf < 4; kf++) {          // K=64, 16 per mma
            int kw = kf * 8 + (lane & 3);
            uint32_t a[2][4];
#pragma unroll
            for (int mf = 0; mf < 2; mf++) {
                int ra = wm * 32 + mf * 16 + (lane >> 2);
                a[mf][0] = sq[ra * QSTW + kw];
                a[mf][1] = sq[(ra + 8) * QSTW + kw];
                a[mf][2] = sq[ra * QSTW + kw + 4];
                a[mf][3] = sq[(ra + 8) * QSTW + kw + 4];
            }
#pragma unroll
            for (int nf = 0; nf < 4; nf++) {
                int rb = wn * 32 + nf * 8 + (lane >> 2);
                uint32_t b[2];
                b[0] = skv[rb * KSTW + kw];
                b[1] = skv[rb * KSTW + kw + 4];
#pragma unroll
                for (int mf = 0; mf < 2; mf++)
                    mma_bf16(num[mf][nf][0], num[mf][nf][1], num[mf][nf][2], num[mf][nf][3],
                             a[mf], b);
            }
        }
#pragma unroll
        for (int mf = 0; mf < 2; mf++) {
            int rl = wm * 32 + mf * 16 + (lane >> 2);
            float i0 = 1.f / sden[rl];
            float i1 = 1.f / sden[rl + 8];
#pragma unroll
            for (int nf = 0; nf < 4; nf++) {
                int col = wn * 32 + nf * 8 + (lane & 3) * 2;
                float s0 = svs[col], s1 = svs[col + 1];
                facc[mf][nf][0] += (scal * num[mf][nf][0] + s0) * i0;
                facc[mf][nf][1] += (scal * num[mf][nf][1] + s1) * i0;
                facc[mf][nf][2] += (scal * num[mf][nf][2] + s0) * i1;
                facc[mf][nf][3] += (scal * num[mf][nf][3] + s1) * i1;
            }
        }
    }
#pragma unroll
    for (int mf = 0; mf < 2; mf++) {
#pragma unroll
        for (int nf = 0; nf < 4; nf++) {
            int row = m0 + wm * 32 + mf * 16 + (lane >> 2);
            int col = wn * 32 + nf * 8 + (lane & 3) * 2;
            if (row < NN)
                *(float2*)&out[(size_t)row * 64 + col] =
                    make_float2(0.25f * facc[mf][nf][0], 0.25f * facc[mf][nf][1]);
            if (row + 8 < NN)
                *(float2*)&out[(size_t)(row + 8) * 64 + col] =
                    make_float2(0.25f * facc[mf][nf][2], 0.25f * facc[mf][nf][3]);
        }
    }
}

__global__ void __launch_bounds__(256)
phase5(float* __restrict__ out, const int* __restrict__ ei, const float* __restrict__ ew) {
    extern __shared__ uint32_t smu[];
    int b = blockIdx.x;
    if (b < P5_ATTN) {
        attn_body(smu, b, out);
    } else {
        // scatter: no deg reads, no rsqrt — raw edge weight into CSR
        int gs = b - P5_ATTN;
        for (int e = gs * 256 + threadIdx.x; e < EE; e += 784 * 256) {
            int r = ei[e];
            int c = ei[EE + e];
            float w = ew[e];
            int slot = atomicAdd(&g_cursor[c], 1);
            g_src[slot] = r;
            g_val[slot] = w;
        }
    }
}

// ======== phase6: GCN gather (atomic-free), scaled by rsq(deg[n]) ========
__global__ void phase6(float* __restrict__ out) {
    int t = threadIdx.x;
    int n = blockIdx.x * 4 + (t >> 6);
    int dd = t & 63;
    if (n >= NN) return;
    int e0 = g_offs[n], e1 = g_offs[n + 1];
    float acc = 0.f;
    for (int e = e0; e < e1; ++e) {
        int r = g_src[e];
        float val = g_val[e];
        acc += val * g_vbar[(size_t)r * 64 + dd];
    }
    float dg = g_deg[n];
    float rsqc = (dg > 0.f) ? rsqrtf(dg) : 0.f;
    out[(size_t)n * 64 + dd] += acc * rsqc;
}

// ---------------- launch ----------------
extern "C" void kernel_launch(void* const* d_in, const int* in_sizes, int n_in,
                              void* d_out, int out_size) {
    const float* query = (const float*)d_in[0];
    const float* source = (const float*)d_in[1];
    const float* Wq = (const float*)d_in[2];
    const float* bq = (const float*)d_in[3];
    const float* Wk = (const float*)d_in[4];
    const float* bk = (const float*)d_in[5];
    const float* Wv = (const float*)d_in[6];
    const float* bv = (const float*)d_in[7];
    const int*   ei = (const int*)d_in[8];
    const float* ew = (const float*)d_in[9];
    float* out = (float*)d_out;

    const int p1_smem = 4 * TSZ * (int)sizeof(float);                        // 73728
    const int p5_smem = (128 * QSTW + 64 * KSTW) * 4 + (128 + 64 + 64) * 4;  // ~26368

    cudaFuncSetAttribute(phase1, cudaFuncAttributeMaxDynamicSharedMemorySize, p1_smem);
    cudaFuncSetAttribute(phase5, cudaFuncAttributeMaxDynamicSharedMemorySize, p5_smem);

    zero_kernel<<<256, 256>>>(Wv, bv);
    phase1<<<P1_TOTAL, 256, p1_smem>>>(query, Wq, bq, source, ei);
    mid<<<MD_TOTAL, 256>>>(Wk, bk, Wv, bv);
    phase5<<<P5_TOTAL, 256, p5_smem>>>(out, ei, ew);
    phase6<<<12500, 256>>>(out);
}

// round 15
// speedup vs baseline: 1.1308x; 1.0145x over previous
#include <cuda_runtime.h>
#include <cuda_bf16.h>
#include <math.h>
#include <stdint.h>

#define NN 50000
#define CC 256
#define HH 4
#define DD 64
#define EE 800000
#define OC 256   // H*D
#define FNN 50000.0f

// ---------------- device scratch ----------------
__device__ uint32_t g_qb[NN * 128];  // q as packed bf16x2 (col pairs)
__device__ float g_vbar[NN * DD];
__device__ float g_S[OC * OC];       // Xs^T Xs (FULL matrix: off-diag dual-written)
__device__ float g_T[OC * OC];       // Wk @ S
__device__ float g_xsum[OC];
__device__ float g_wvbar[DD * CC];
__device__ float g_bvbar[DD];
__device__ float g_ksum[OC];
__device__ float g_vsum[OC];
__device__ float g_kv[HH * DD * DD]; // [h][d][m]
__device__ float g_scal[2];
__device__ float g_deg[NN];
__device__ int   g_offs[NN + 1];
__device__ int   g_cursor[NN];
__device__ unsigned long long g_edge[EE];   // packed: hi32 = weight bits, lo32 = src row
__device__ int   g_part[256];
__device__ int   g_cnt[16];

// dependency counters (used inside `mid` launch only)
#define C_FIXT 0
#define C_SUMV 1
#define C_SC1  2
#define C_SC2  3

__device__ __forceinline__ void done_inc(int idx) {
    __threadfence();
    __syncthreads();
    if (threadIdx.x == 0) atomicAdd(&g_cnt[idx], 1);
}
__device__ __forceinline__ void spin_on(int idx, int target) {
    if (threadIdx.x == 0) {
        while (atomicAdd(&g_cnt[idx], 0) < target) { __nanosleep(64); }
    }
    __syncthreads();
}

// ---------------- helpers ----------------
__device__ __forceinline__ uint32_t f2tf32(float x) {
    uint32_t r;
    asm("cvt.rna.tf32.f32 %0, %1;" : "=r"(r) : "f"(x));
    return r;
}
__device__ __forceinline__ uint32_t pk(float lo, float hi) {
    uint32_t r;
    asm("cvt.rn.bf16x2.f32 %0, %1, %2;" : "=r"(r) : "f"(hi), "f"(lo));
    return r;
}
__device__ __forceinline__ void mma_tf32(float& d0, float& d1, float& d2, float& d3,
                                         const uint32_t* a, const uint32_t* b) {
    asm volatile(
        "mma.sync.aligned.m16n8k8.row.col.f32.tf32.tf32.f32 "
        "{%0,%1,%2,%3}, {%4,%5,%6,%7}, {%8,%9}, {%0,%1,%2,%3};\n"
        : "+f"(d0), "+f"(d1), "+f"(d2), "+f"(d3)
        : "r"(a[0]), "r"(a[1]), "r"(a[2]), "r"(a[3]), "r"(b[0]), "r"(b[1]));
}
__device__ __forceinline__ void mma_bf16(float& d0, float& d1, float& d2, float& d3,
                                         const uint32_t* a, const uint32_t* b) {
    asm volatile(
        "mma.sync.aligned.m16n8k16.row.col.f32.bf16.bf16.f32 "
        "{%0,%1,%2,%3}, {%4,%5,%6,%7}, {%8,%9}, {%0,%1,%2,%3};\n"
        : "+f"(d0), "+f"(d1), "+f"(d2), "+f"(d3)
        : "r"(a[0]), "r"(a[1]), "r"(a[2]), "r"(a[3]), "r"(b[0]), "r"(b[1]));
}

// ---------------- L1: zero scratch + counters + Wvbar prep ----------------
__global__ void zero_kernel(const float* __restrict__ Wv, const float* __restrict__ bv) {
    int i = blockIdx.x * 256 + threadIdx.x;   // 65536
    g_S[i] = 0.f;
    if (i < NN) g_deg[i] = 0.f;
    if (i < OC) g_xsum[i] = 0.f;
    if (i < 2) g_scal[i] = 0.f;
    if (i < 16) g_cnt[i] = 0;
    if (i < DD * CC) {
        int d = i >> 8, c = i & 255;
        g_wvbar[i] = 0.25f * (Wv[(d) * CC + c] + Wv[(d + 64) * CC + c] +
                              Wv[(d + 128) * CC + c] + Wv[(d + 192) * CC + c]);
    }
    if (i < DD)
        g_bvbar[i] = 0.25f * (bv[i] + bv[i + 64] + bv[i + 128] + bv[i + 192]);
}

// ======================== phase1 bodies ========================
#define BK 32
#define AST 36
#define TSZ (128 * AST)
#define SST 132
#define CHK 1024
#define NCH 49

// ---- SYRK tile body (off-diag also writes transposed tile -> S is FULL) ----
__device__ void syrk_body(float* smf, int bidx, const float* __restrict__ Xs) {
    float* Ai = smf;
    float* Bj = smf + 2 * 32 * SST;
    int t = threadIdx.x;
    int tile = bidx / NCH;            // 0:(0,0) 1:(0,1) 2:(1,1)
    int chunk = bidx % NCH;
    int ci = (tile == 2) ? 1 : 0;
    int cj = (tile == 0) ? 0 : 1;
    int diag = (ci == cj);
    int nbase = chunk * CHK;
    int lane = t & 31, warp = t >> 5;
    int wm = warp & 1, wn = warp >> 1;

    auto load_tile = [&](int stage, int s) {
#pragma unroll
        for (int p = 0; p < 4; p++) {
            int idx = p * 256 + t;
            int r = idx >> 5;
            int c4 = (idx & 31) * 4;
            int node = nbase + s + r;
            int ok = (node < NN);
            const float* srcA = Xs + (size_t)(ok ? node : 0) * CC + ci * 128 + c4;
            uint32_t da = (uint32_t)__cvta_generic_to_shared(&Ai[stage * 32 * SST + r * SST + c4]);
            int sz = ok ? 16 : 0;
            asm volatile("cp.async.cg.shared.global [%0], [%1], 16, %2;\n"
                         :: "r"(da), "l"(srcA), "r"(sz));
            if (!diag) {
                const float* srcB = Xs + (size_t)(ok ? node : 0) * CC + cj * 128 + c4;
                uint32_t db = (uint32_t)__cvta_generic_to_shared(&Bj[stage * 32 * SST + r * SST + c4]);
                asm volatile("cp.async.cg.shared.global [%0], [%1], 16, %2;\n"
                             :: "r"(db), "l"(srcB), "r"(sz));
            }
        }
        asm volatile("cp.async.commit_group;\n");
    };

    float d[4][4][4];
#pragma unroll
    for (int i = 0; i < 4; i++)
#pragma unroll
        for (int j = 0; j < 4; j++)
#pragma unroll
            for (int c = 0; c < 4; c++) d[i][j][c] = 0.f;

    load_tile(0, 0);
    for (int si = 0; si < CHK / 32; si++) {
        if (si < CHK / 32 - 1) {
            load_tile((si + 1) & 1, (si + 1) * 32);
            asm volatile("cp.async.wait_group 1;\n");
        } else {
            asm volatile("cp.async.wait_group 0;\n");
        }
        __syncthreads();
        const float* Af = Ai + (si & 1) * 32 * SST;
        const float* Bf = diag ? Af : (Bj + (si & 1) * 32 * SST);
#pragma unroll
        for (int kf = 0; kf < 2; kf++) {
            int k = kf * 16 + (lane & 3) * 2;
            uint32_t a[4][4], b[4][2];
#pragma unroll
            for (int mf = 0; mf < 4; mf++) {
                int ra = wm * 64 + mf * 16 + (lane >> 2);
                a[mf][0] = pk(Af[k * SST + ra],       Af[(k + 1) * SST + ra]);
                a[mf][1] = pk(Af[k * SST + ra + 8],   Af[(k + 1) * SST + ra + 8]);
                a[mf][2] = pk(Af[(k + 8) * SST + ra], Af[(k + 9) * SST + ra]);
                a[mf][3] = pk(Af[(k + 8) * SST + ra + 8], Af[(k + 9) * SST + ra + 8]);
            }
#pragma unroll
            for (int nf = 0; nf < 4; nf++) {
                int rb = wn * 32 + nf * 8 + (lane >> 2);
                b[nf][0] = pk(Bf[k * SST + rb],       Bf[(k + 1) * SST + rb]);
                b[nf][1] = pk(Bf[(k + 8) * SST + rb], Bf[(k + 9) * SST + rb]);
            }
#pragma unroll
            for (int nf = 0; nf < 4; nf++)
#pragma unroll
                for (int mf = 0; mf < 4; mf++)
                    mma_bf16(d[mf][nf][0], d[mf][nf][1], d[mf][nf][2], d[mf][nf][3],
                             a[mf], b[nf]);
        }
        __syncthreads();
    }
#pragma unroll
    for (int mf = 0; mf < 4; mf++) {
#pragma unroll
        for (int nf = 0; nf < 4; nf++) {
            int row = ci * 128 + wm * 64 + mf * 16 + (lane >> 2);
            int col = cj * 128 + wn * 32 + nf * 8 + (lane & 3) * 2;
            atomicAdd(&g_S[row * 256 + col],       d[mf][nf][0]);
            atomicAdd(&g_S[row * 256 + col + 1],   d[mf][nf][1]);
            atomicAdd(&g_S[(row + 8) * 256 + col], d[mf][nf][2]);
            atomicAdd(&g_S[(row + 8) * 256 + col + 1], d[mf][nf][3]);
            if (!diag) {   // dual-write transposed tile so S is full
                atomicAdd(&g_S[col * 256 + row],           d[mf][nf][0]);
                atomicAdd(&g_S[(col + 1) * 256 + row],     d[mf][nf][1]);
                atomicAdd(&g_S[col * 256 + row + 8],       d[mf][nf][2]);
                atomicAdd(&g_S[(col + 1) * 256 + row + 8], d[mf][nf][3]);
            }
        }
    }
}

// ---- Q GEMM body (bf16, writes packed bf16 q) ----
__device__ void gemmq_body(float* smf, int bi, const float* __restrict__ X,
                           const float* __restrict__ W, const float* __restrict__ B) {
    float* As = smf;
    float* Bs = smf + 2 * TSZ;
    __shared__ float red8[8];

    int t = threadIdx.x;
    int m0 = (bi >> 1) * 128;
    int n0 = (bi & 1) * 128;
    int lane = t & 31, warp = t >> 5;
    int wm = warp & 1, wn = warp >> 1;
    int lr = t >> 3, lc = (t & 7) * 4;

    auto load_tile = [&](int stage, int k0) {
#pragma unroll
        for (int p = 0; p < 4; p++) {
            int r = p * 32 + lr;
            int gr = m0 + r;
            int ok = (gr < NN);
            const float* srcA = X + (size_t)(ok ? gr : 0) * CC + k0 + lc;
            uint32_t da = (uint32_t)__cvta_generic_to_shared(&As[stage * TSZ + r * AST + lc]);
            int szA = ok ? 16 : 0;
            asm volatile("cp.async.cg.shared.global [%0], [%1], 16, %2;\n"
                         :: "r"(da), "l"(srcA), "r"(szA));
            const float* srcB = W + (size_t)(n0 + r) * CC + k0 + lc;
            uint32_t db = (uint32_t)__cvta_generic_to_shared(&Bs[stage * TSZ + r * AST + lc]);
            asm volatile("cp.async.cg.shared.global [%0], [%1], 16;\n"
                         :: "r"(db), "l"(srcB));
        }
        asm volatile("cp.async.commit_group;\n");
    };

    float d[4][4][4];
#pragma unroll
    for (int i = 0; i < 4; i++)
#pragma unroll
        for (int j = 0; j < 4; j++)
#pragma unroll
            for (int c = 0; c < 4; c++) d[i][j][c] = 0.f;

    load_tile(0, 0);
    for (int ki = 0; ki < CC / BK; ki++) {
        if (ki < CC / BK - 1) {
            load_tile((ki + 1) & 1, (ki + 1) * BK);
            asm volatile("cp.async.wait_group 1;\n");
        } else {
            asm volatile("cp.async.wait_group 0;\n");
        }
        __syncthreads();
        const float* Af = As + (ki & 1) * TSZ;
        const float* Bf = Bs + (ki & 1) * TSZ;
#pragma unroll
        for (int kf = 0; kf < 2; kf++) {
            int ka = kf * 16 + (lane & 3) * 2;
            uint32_t a[4][4], b[4][2];
#pragma unroll
            for (int mf = 0; mf < 4; mf++) {
                int ra = wm * 64 + mf * 16 + (lane >> 2);
                float2 x0 = *(const float2*)&Af[ra * AST + ka];
                float2 x1 = *(const float2*)&Af[(ra + 8) * AST + ka];
                float2 x2 = *(const float2*)&Af[ra * AST + ka + 8];
                float2 x3 = *(const float2*)&Af[(ra + 8) * AST + ka + 8];
                a[mf][0] = pk(x0.x, x0.y); a[mf][1] = pk(x1.x, x1.y);
                a[mf][2] = pk(x2.x, x2.y); a[mf][3] = pk(x3.x, x3.y);
            }
#pragma unroll
            for (int nf = 0; nf < 4; nf++) {
                int rb = wn * 32 + nf * 8 + (lane >> 2);
                float2 y0 = *(const float2*)&Bf[rb * AST + ka];
                float2 y1 = *(const float2*)&Bf[rb * AST + ka + 8];
                b[nf][0] = pk(y0.x, y0.y); b[nf][1] = pk(y1.x, y1.y);
            }
#pragma unroll
            for (int nf = 0; nf < 4; nf++)
#pragma unroll
                for (int mf = 0; mf < 4; mf++)
                    mma_bf16(d[mf][nf][0], d[mf][nf][1], d[mf][nf][2], d[mf][nf][3],
                             a[mf], b[nf]);
        }
        __syncthreads();
    }

    float qs = 0.f;
#pragma unroll
    for (int mf = 0; mf < 4; mf++) {
#pragma unroll
        for (int nf = 0; nf < 4; nf++) {
            int row = m0 + wm * 64 + mf * 16 + (lane >> 2);
            int col = n0 + wn * 32 + nf * 8 + (lane & 3) * 2;
            float bi0 = B[col], bi1 = B[col + 1];
            if (row < NN) {
                float o0 = d[mf][nf][0] + bi0, o1 = d[mf][nf][1] + bi1;
                g_qb[(size_t)row * 128 + (col >> 1)] = pk(o0, o1);
                qs += o0 * o0 + o1 * o1;
            }
            if (row + 8 < NN) {
                float o0 = d[mf][nf][2] + bi0, o1 = d[mf][nf][3] + bi1;
                g_qb[(size_t)(row + 8) * 128 + (col >> 1)] = pk(o0, o1);
                qs += o0 * o0 + o1 * o1;
            }
        }
    }
#pragma unroll
    for (int off = 16; off > 0; off >>= 1) qs += __shfl_xor_sync(0xffffffffu, qs, off);
    if (lane == 0) red8[warp] = qs;
    __syncthreads();
    if (t == 0) {
        float s = 0.f;
#pragma unroll
        for (int j = 0; j < 8; j++) s += red8[j];
        atomicAdd(&g_scal[0], s);
    }
}

// ---- vbar GEMM body (tf32) + xsum fold ----
__device__ void vbar_body(float* smf, int bi, const float* __restrict__ Xs) {
    float* As = smf;
    float* Bs = smf + 2 * TSZ;

    int t = threadIdx.x;
    int m0 = bi * 128;
    int lane = t & 31, warp = t >> 5;
    int lr = t >> 3, lc = (t & 7) * 4;

    auto load_tile = [&](int stage, int k0) {
#pragma unroll
        for (int p = 0; p < 4; p++) {
            int r = p * 32 + lr;
            int gr = m0 + r;
            int ok = (gr < NN);
            const float* srcA = Xs + (size_t)(ok ? gr : 0) * CC + k0 + lc;
            uint32_t da = (uint32_t)__cvta_generic_to_shared(&As[stage * TSZ + r * AST + lc]);
            int szA = ok ? 16 : 0;
            asm volatile("cp.async.cg.shared.global [%0], [%1], 16, %2;\n"
                         :: "r"(da), "l"(srcA), "r"(szA));
        }
#pragma unroll
        for (int p = 0; p < 2; p++) {
            int r = p * 32 + lr;
            const float* srcB = g_wvbar + (size_t)r * CC + k0 + lc;
            uint32_t db = (uint32_t)__cvta_generic_to_shared(&Bs[stage * 64 * AST + r * AST + lc]);
            asm volatile("cp.async.cg.shared.global [%0], [%1], 16;\n"
                         :: "r"(db), "l"(srcB));
        }
        asm volatile("cp.async.commit_group;\n");
    };

    float acc[8][4];
#pragma unroll
    for (int i = 0; i < 8; i++)
#pragma unroll
        for (int c = 0; c < 4; c++) acc[i][c] = 0.f;

    load_tile(0, 0);
    for (int ki = 0; ki < CC / BK; ki++) {
        if (ki < CC / BK - 1) {
            load_tile((ki + 1) & 1, (ki + 1) * BK);
            asm volatile("cp.async.wait_group 1;\n");
        } else {
            asm volatile("cp.async.wait_group 0;\n");
        }
        __syncthreads();
        const float* Af = As + (ki & 1) * TSZ;
        const float* Bf = Bs + (ki & 1) * 64 * AST;
        {
            int col = t & 31, rg = t >> 5;
            float p = 0.f;
#pragma unroll
            for (int r = 0; r < 16; r++) p += Af[(rg * 16 + r) * AST + col];
            atomicAdd(&g_xsum[ki * 32 + col], p);
        }
#pragma unroll
        for (int kf = 0; kf < 4; kf++) {
            int ka = kf * 8 + (lane & 3);
            uint32_t a[4];
            int ra = warp * 16 + (lane >> 2);
            a[0] = f2tf32(Af[ra * AST + ka]);
            a[1] = f2tf32(Af[(ra + 8) * AST + ka]);
            a[2] = f2tf32(Af[ra * AST + ka + 4]);
            a[3] = f2tf32(Af[(ra + 8) * AST + ka + 4]);
#pragma unroll
            for (int nf = 0; nf < 8; nf++) {
                int rb = nf * 8 + (lane >> 2);
                uint32_t b[2];
                b[0] = f2tf32(Bf[rb * AST + ka]);
                b[1] = f2tf32(Bf[rb * AST + ka + 4]);
                mma_tf32(acc[nf][0], acc[nf][1], acc[nf][2], acc[nf][3], a, b);
            }
        }
        __syncthreads();
    }
#pragma unroll
    for (int nf = 0; nf < 8; nf++) {
        int row = m0 + warp * 16 + (lane >> 2);
        int col = nf * 8 + (lane & 3) * 2;
        float b0 = g_bvbar[col], b1 = g_bvbar[col + 1];
        if (row < NN)
            *(float2*)&g_vbar[(size_t)row * DD + col] =
                make_float2(acc[nf][0] + b0, acc[nf][1] + b1);
        if (row + 8 < NN)
            *(float2*)&g_vbar[(size_t)(row + 8) * DD + col] =
                make_float2(acc[nf][2] + b0, acc[nf][3] + b1);
    }
}

// ---- phase1 dispatcher: syrk(147) | gemm_q(782) | vbar(391) | degree(391) ----
#define P1_SYRK 147
#define P1_GEMM (P1_SYRK + 782)   // 929
#define P1_VBAR (P1_GEMM + 391)   // 1320
#define P1_TOTAL (P1_VBAR + 391)  // 1711

__global__ void __launch_bounds__(256, 2)
phase1(const float* __restrict__ Xq, const float* __restrict__ Wq, const float* __restrict__ bq,
       const float* __restrict__ Xs, const int* __restrict__ ei)
{
    extern __shared__ float smf[];
    int b = blockIdx.x;
    if (b < P1_SYRK) {
        syrk_body(smf, b, Xs);
    } else if (b < P1_GEMM) {
        gemmq_body(smf, b - P1_SYRK, Xq, Wq, bq);
    } else if (b < P1_VBAR) {
        vbar_body(smf, b - P1_GEMM, Xs);
    } else {
        int gs = b - P1_VBAR;
        for (int e = gs * 256 + threadIdx.x; e < EE; e += 391 * 256)
            atomicAdd(&g_deg[ei[EE + e]], 1.0f);
    }
}

// ======== mid: fixT|scan1|sumvec|scan2|kv|ksq|scan3|vb2 ========
#define MD_FIXT 256
#define MD_SC1  (MD_FIXT + 196)  // 452
#define MD_SUMV (MD_SC1 + 2)     // 454
#define MD_SC2  (MD_SUMV + 1)    // 455
#define MD_KV   (MD_SC2 + 2048)  // 2503
#define MD_KSQ  (MD_KV + 64)     // 2567
#define MD_SC3  (MD_KSQ + 196)   // 2763
#define MD_VB2G 784
#define MD_TOTAL (MD_SC3 + MD_VB2G)  // 3547

__global__ void __launch_bounds__(256)
mid(const float* __restrict__ Wk, const float* __restrict__ bk,
    const float* __restrict__ Wv, const float* __restrict__ bv)
{
    int b = blockIdx.x, t = threadIdx.x;
    if (b < MD_FIXT) {
        // fixT: T = Wk @ S (S full -> coalesced reads)
        __shared__ float w[256];
        w[t] = Wk[b * CC + t];
        __syncthreads();
        float acc = 0.f;
#pragma unroll 4
        for (int c = 0; c < 256; c++)
            acc += w[c] * g_S[c * 256 + t];
        g_T[b * 256 + t] = acc;
        done_inc(C_FIXT);
    } else if (b < MD_SC1) {
        int blk = b - MD_FIXT;
        int i = blk * 256 + t;
        int v = (i < NN) ? (int)g_deg[i] : 0;
#pragma unroll
        for (int off = 16; off > 0; off >>= 1) v += __shfl_xor_sync(0xffffffffu, v, off);
        __shared__ int ws[8];
        if ((t & 31) == 0) ws[t >> 5] = v;
        __syncthreads();
        if (t == 0) {
            int s = 0;
#pragma unroll
            for (int j = 0; j < 8; j++) s += ws[j];
            g_part[blk] = s;
        }
        done_inc(C_SC1);
    } else if (b < MD_SUMV) {
        int sel = b - MD_SC1;
        __shared__ float xs[256];
        xs[t] = g_xsum[t];
        __syncthreads();
        const float* W = sel ? Wv : Wk;
        const float* bb = sel ? bv : bk;
        float* dst = sel ? g_vsum : g_ksum;
        float acc = 0.f;
#pragma unroll 4
        for (int c = 0; c < 256; c++) acc += W[t * CC + c] * xs[c];
        dst[t] = acc + FNN * bb[t];
        done_inc(C_SUMV);
    } else if (b < MD_SC2) {
        spin_on(C_SC1, 196);
        int v = (t < 196) ? g_part[t] : 0;
        int lane = t & 31, w = t >> 5;
        int x = v;
#pragma unroll
        for (int off = 1; off < 32; off <<= 1) {
            int y = __shfl_up_sync(0xffffffffu, x, off);
            if (lane >= off) x += y;
        }
        __shared__ int ws[8];
        if (lane == 31) ws[w] = x;
        __syncthreads();
        if (t == 0) {
            int c = 0;
#pragma unroll
            for (int j = 0; j < 8; j++) { int tmp = ws[j]; ws[j] = c; c += tmp; }
        }
        __syncthreads();
        int incl = x + ws[w];
        if (t < 196) g_part[t] = incl - v;
        if (t == 0) g_offs[NN] = EE;
        done_inc(C_SC2);
    } else if (b < MD_KV) {
        spin_on(C_FIXT, 256);
        spin_on(C_SUMV, 2);
        // one warp per kv element, coalesced float4 dot over 256
        int wid = (b - MD_SC2) * 8 + (t >> 5);   // 0..16383
        int lane = t & 31;
        int h = wid >> 12, rem = wid & 4095;
        int dd = rem >> 6, m = rem & 63;
        int rk = h * 64 + m, rv = h * 64 + dd;
        const float4* Tp = (const float4*)&g_T[rk * 256];
        const float4* Wp = (const float4*)&Wv[(size_t)rv * CC];
        float4 t0 = Tp[lane], t1 = Tp[lane + 32];
        float4 w0 = Wp[lane], w1 = Wp[lane + 32];
        float acc = t0.x * w0.x + t0.y * w0.y + t0.z * w0.z + t0.w * w0.w
                  + t1.x * w1.x + t1.y * w1.y + t1.z * w1.z + t1.w * w1.w;
#pragma unroll
        for (int off = 16; off > 0; off >>= 1) acc += __shfl_xor_sync(0xffffffffu, acc, off);
        if (lane == 0) {
            float kx = g_ksum[rk] - FNN * bk[rk];
            float vx = g_vsum[rv] - FNN * bv[rv];
            g_kv[h * 4096 + dd * 64 + m] =
                acc + kx * bv[rv] + bk[rk] * vx + FNN * bk[rk] * bv[rv];
        }
    } else if (b < MD_KSQ) {
        spin_on(C_FIXT, 256);
        spin_on(C_SUMV, 2);
        int p = b - MD_KV;
        float acc = 0.f;
#pragma unroll
        for (int j = 0; j < 4; j++) {
            int idx = p * 1024 + j * 256 + t;
            acc += g_T[idx] * Wk[idx];
        }
#pragma unroll
        for (int off = 16; off > 0; off >>= 1) acc += __shfl_xor_sync(0xffffffffu, acc, off);
        __shared__ float r8[8];
        if ((t & 31) == 0) r8[t >> 5] = acc;
        __syncthreads();
        if (t == 0) {
            float s = 0.f;
#pragma unroll
            for (int j = 0; j < 8; j++) s += r8[j];
            if (p == 0) {
                float e = 0.f;
                for (int i = 0; i < 256; i++) {
                    float kx = g_ksum[i] - FNN * bk[i];
                    e += 2.f * bk[i] * kx + FNN * bk[i] * bk[i];
                }
                s += e;
            }
            atomicAdd(&g_scal[1], s);
        }
    } else if (b < MD_SC3) {
        // scan3
        spin_on(C_SC2, 1);
        int blk = b - MD_KSQ;
        int i = blk * 256 + t;
        int v = (i < NN) ? (int)g_deg[i] : 0;
        int lane = t & 31, w = t >> 5;
        int x = v;
#pragma unroll
        for (int off = 1; off < 32; off <<= 1) {
            int y = __shfl_up_sync(0xffffffffu, x, off);
            if (lane >= off) x += y;
        }
        __shared__ int ws[8];
        if (lane == 31) ws[w] = x;
        __syncthreads();
        if (t == 0) {
            int c = 0;
#pragma unroll
            for (int j = 0; j < 8; j++) { int tmp = ws[j]; ws[j] = c; c += tmp; }
        }
        __syncthreads();
        int excl = (x - v) + ws[w] + g_part[blk];
        if (i < NN) { g_offs[i] = excl; g_cursor[i] = excl; }
    } else {
        // vb2: vbar[n] *= (deg[n]>0 ? rsqrt(deg[n]) : 0)  — deg & vbar ready pre-launch
        int gs = b - MD_SC3;
        const int TOT = NN * 16;   // float4 units
        for (int i = gs * 256 + t; i < TOT; i += MD_VB2G * 256) {
            int n = i >> 4;
            float dg = g_deg[n];
            float sc = (dg > 0.f) ? rsqrtf(dg) : 0.f;
            float4* p = (float4*)&g_vbar[(size_t)i * 4];
            float4 v = *p;
            v.x *= sc; v.y *= sc; v.z *= sc; v.w *= sc;
            *p = v;
        }
    }
}

// ======== phase5: attn (bf16 MMA, 391) | scatter (784 grid-stride) ========
#define QSTW 33   // q smem row stride in uint32 words (32 data + 1 pad)
#define KSTW 33
#define P5_ATTN 391
#define P5_TOTAL (P5_ATTN + 784)

__device__ void attn_body(uint32_t* sm, int bi, float* __restrict__ out) {
    uint32_t* sq  = sm;                      // 128 x QSTW (bf16x2 words)
    uint32_t* skv = sm + 128 * QSTW;         // 64 x KSTW
    float* sden = (float*)(skv + 64 * KSTW); // 128
    float* sks  = sden + 128;                // 64
    float* svs  = sks + 64;                  // 64

    int t = threadIdx.x;
    int lane = t & 31, warp = t >> 5;
    int wm = warp >> 1;         // 0..3: 32-row band
    int wn = warp & 1;          // 0..1: 32-col band
    int m0 = bi * 128;
    float scal = rsqrtf(g_scal[0]) * rsqrtf(g_scal[1]);

    float facc[2][4][4];
#pragma unroll
    for (int i = 0; i < 2; i++)
#pragma unroll
        for (int j = 0; j < 4; j++)
#pragma unroll
            for (int c = 0; c < 4; c++) facc[i][j][c] = 0.f;

    for (int h = 0; h < HH; h++) {
        __syncthreads();
        {
            int r = t >> 1, half = (t & 1) * 16;
            int n = m0 + r;
#pragma unroll
            for (int j = 0; j < 4; j++) {
                uint4 u = make_uint4(0u, 0u, 0u, 0u);
                if (n < NN)
                    u = *(const uint4*)&g_qb[(size_t)n * 128 + h * 32 + half + j * 4];
                uint32_t* dst = &sq[r * QSTW + half + j * 4];
                dst[0] = u.x; dst[1] = u.y; dst[2] = u.z; dst[3] = u.w;
            }
            int kr = t >> 2, kq = (t & 3) * 16;
#pragma unroll
            for (int j = 0; j < 4; j++) {
                float4 v = *(const float4*)&g_kv[h * 4096 + kr * 64 + kq + j * 4];
                uint32_t* dst = &skv[kr * KSTW + (kq >> 1) + j * 2];
                dst[0] = pk(v.x, v.y);
                dst[1] = pk(v.z, v.w);
            }
            if (t < 64) { sks[t] = g_ksum[h * 64 + t]; svs[t] = g_vsum[h * 64 + t]; }
        }
        __syncthreads();
        {
            int r = t >> 1, p = t & 1;
            float s = 0.f;
#pragma unroll
            for (int w = 0; w < 16; w++) {
                uint32_t word = sq[r * QSTW + p * 16 + w];
                __nv_bfloat162 bb = *reinterpret_cast<__nv_bfloat162*>(&word);
                s += __bfloat162float(bb.x) * sks[p * 32 + 2 * w]
                   + __bfloat162float(bb.y) * sks[p * 32 + 2 * w + 1];
            }
            s += __shfl_xor_sync(0xffffffffu, s, 1);
            if (p == 0) sden[r] = scal * s + FNN;
        }
        __syncthreads();

        float num[2][4][4];
#pragma unroll
        for (int i = 0; i < 2; i++)
#pragma unroll
            for (int j = 0; j < 4; j++)
#pragma unroll
                for (int c = 0; c < 4; c++) num[i][j][c] = 0.f;

#pragma unroll
        for (int kf = 0; kf < 4; kf++) {          // K=64, 16 per mma
            int kw = kf * 8 + (lane & 3);
            uint32_t a[2][4];
#pragma unroll
            for (int mf = 0; mf < 2; mf++) {
                int ra = wm * 32 + mf * 16 + (lane >> 2);
                a[mf][0] = sq[ra * QSTW + kw];
                a[mf][1] = sq[(ra + 8) * QSTW + kw];
                a[mf][2] = sq[ra * QSTW + kw + 4];
                a[mf][3] = sq[(ra + 8) * QSTW + kw + 4];
            }
#pragma unroll
            for (int nf = 0; nf < 4; nf++) {
                int rb = wn * 32 + nf * 8 + (lane >> 2);
                uint32_t b[2];
                b[0] = skv[rb * KSTW + kw];
                b[1] = skv[rb * KSTW + kw + 4];
#pragma unroll
                for (int mf = 0; mf < 2; mf++)
                    mma_bf16(num[mf][nf][0], num[mf][nf][1], num[mf][nf][2], num[mf][nf][3],
                             a[mf], b);
            }
        }
#pragma unroll
        for (int mf = 0; mf < 2; mf++) {
            int rl = wm * 32 + mf * 16 + (lane >> 2);
            float i0 = 1.f / sden[rl];
            float i1 = 1.f / sden[rl + 8];
#pragma unroll
            for (int nf = 0; nf < 4; nf++) {
                int col = wn * 32 + nf * 8 + (lane & 3) * 2;
                float s0 = svs[col], s1 = svs[col + 1];
                facc[mf][nf][0] += (scal * num[mf][nf][0] + s0) * i0;
                facc[mf][nf][1] += (scal * num[mf][nf][1] + s1) * i0;
                facc[mf][nf][2] += (scal * num[mf][nf][2] + s0) * i1;
                facc[mf][nf][3] += (scal * num[mf][nf][3] + s1) * i1;
            }
        }
    }
#pragma unroll
    for (int mf = 0; mf < 2; mf++) {
#pragma unroll
        for (int nf = 0; nf < 4; nf++) {
            int row = m0 + wm * 32 + mf * 16 + (lane >> 2);
            int col = wn * 32 + nf * 8 + (lane & 3) * 2;
            if (row < NN)
                *(float2*)&out[(size_t)row * 64 + col] =
                    make_float2(0.25f * facc[mf][nf][0], 0.25f * facc[mf][nf][1]);
            if (row + 8 < NN)
                *(float2*)&out[(size_t)(row + 8) * 64 + col] =
                    make_float2(0.25f * facc[mf][nf][2], 0.25f * facc[mf][nf][3]);
        }
    }
}

__global__ void __launch_bounds__(256)
phase5(float* __restrict__ out, const int* __restrict__ ei, const float* __restrict__ ew) {
    extern __shared__ uint32_t smu[];
    int b = blockIdx.x;
    if (b < P5_ATTN) {
        attn_body(smu, b, out);
    } else {
        // scatter: packed single 8B store per edge (src + raw weight)
        int gs = b - P5_ATTN;
        for (int e = gs * 256 + threadIdx.x; e < EE; e += 784 * 256) {
            int r = ei[e];
            int c = ei[EE + e];
            float w = ew[e];
            int slot = atomicAdd(&g_cursor[c], 1);
            unsigned long long pkd =
                ((unsigned long long)__float_as_uint(w) << 32) | (unsigned int)r;
            g_edge[slot] = pkd;
        }
    }
}

// ======== phase6: GCN gather (atomic-free), scaled by rsq(deg[n]) ========
__global__ void phase6(float* __restrict__ out) {
    int t = threadIdx.x;
    int n = blockIdx.x * 4 + (t >> 6);
    int dd = t & 63;
    if (n >= NN) return;
    int e0 = g_offs[n], e1 = g_offs[n + 1];
    float acc = 0.f;
    for (int e = e0; e < e1; ++e) {
        unsigned long long pkd = g_edge[e];
        int r = (int)(unsigned int)(pkd & 0xffffffffu);
        float val = __uint_as_float((uint32_t)(pkd >> 32));
        acc += val * g_vbar[(size_t)r * 64 + dd];
    }
    float dg = g_deg[n];
    float rsqc = (dg > 0.f) ? rsqrtf(dg) : 0.f;
    out[(size_t)n * 64 + dd] += acc * rsqc;
}

// ---------------- launch ----------------
extern "C" void kernel_launch(void* const* d_in, const int* in_sizes, int n_in,
                              void* d_out, int out_size) {
    const float* query = (const float*)d_in[0];
    const float* source = (const float*)d_in[1];
    const float* Wq = (const float*)d_in[2];
    const float* bq = (const float*)d_in[3];
    const float* Wk = (const float*)d_in[4];
    const float* bk = (const float*)d_in[5];
    const float* Wv = (const float*)d_in[6];
    const float* bv = (const float*)d_in[7];
    const int*   ei = (const int*)d_in[8];
    const float* ew = (const float*)d_in[9];
    float* out = (float*)d_out;

    const int p1_smem = 4 * TSZ * (int)sizeof(float);                        // 73728
    const int p5_smem = (128 * QSTW + 64 * KSTW) * 4 + (128 + 64 + 64) * 4;  // ~26368

    cudaFuncSetAttribute(phase1, cudaFuncAttributeMaxDynamicSharedMemorySize, p1_smem);
    cudaFuncSetAttribute(phase5, cudaFuncAttributeMaxDynamicSharedMemorySize, p5_smem);

    zero_kernel<<<256, 256>>>(Wv, bv);
    phase1<<<P1_TOTAL, 256, p1_smem>>>(query, Wq, bq, source, ei);
    mid<<<MD_TOTAL, 256>>>(Wk, bk, Wv, bv);
    phase5<<<P5_TOTAL, 256, p5_smem>>>(out, ei, ew);
    phase6<<<12500, 256>>>(out);
}